// round 5
// baseline (speedup 1.0000x reference)
#include <cuda_runtime.h>
#include <cuda_bf16.h>
#include <math.h>
#include <stdint.h>

#define BATCH   2
#define SEQLEN  2048
#define NTOK    (BATCH*SEQLEN)        // 4096
#define DMODEL  768
#define DINNER  1536
#define DSTATE  128
#define HEADDIM 64
#define NHEADS  24
#define CONVDIM 1792                  // DINNER + 2*DSTATE
#define DINPROJ 3352                  // 2*DINNER + 2*DSTATE + NHEADS
#define NSEG    8
#define SEGLEN  (SEQLEN/NSEG)         // 256

// ---------------------------------------------------------------------------
// Scratch buffers (device globals — no allocations allowed)
// ---------------------------------------------------------------------------
__device__ __align__(128) float g_zx[NTOK * DINPROJ];     // in_proj output
__device__ __align__(128) float g_conv[NTOK * CONVDIM];   // conv+silu output (x | B | C)
__device__ __align__(128) float g_dt[NTOK * NHEADS];      // softplus(dt + bias)
__device__ __align__(128) float g_dA[NTOK * NHEADS];      // exp(dt * A)
__device__ __align__(128) float g_cumP[NTOK * NHEADS];    // within-seg cumprod of dA
__device__ __align__(128) float g_y[NTOK * DINNER];       // scan output (atomics)
__device__ __align__(128) float g_fstate[NSEG*BATCH*NHEADS*HEADDIM*DSTATE]; // seg-final local states
__device__ __align__(128) float g_istate[NSEG*BATCH*NHEADS*HEADDIM*DSTATE]; // seg-initial true states

// bf16 hi/lo split operands for tensor-core GEMMs
__device__ __align__(128) __nv_bfloat16 g_u_hi[NTOK * DMODEL];
__device__ __align__(128) __nv_bfloat16 g_u_lo[NTOK * DMODEL];
__device__ __align__(128) __nv_bfloat16 g_w1_hi[DINPROJ * DMODEL];
__device__ __align__(128) __nv_bfloat16 g_w1_lo[DINPROJ * DMODEL];
__device__ __align__(128) __nv_bfloat16 g_w2_hi[DMODEL * DINNER];
__device__ __align__(128) __nv_bfloat16 g_w2_lo[DMODEL * DINNER];
__device__ __align__(128) __nv_bfloat16 g_yn_hi[NTOK * DINNER];
__device__ __align__(128) __nv_bfloat16 g_yn_lo[NTOK * DINNER];

// ---------------------------------------------------------------------------
// MMA helpers (baseline PTX — works under compute_103 virtual arch)
// ---------------------------------------------------------------------------
static __device__ __forceinline__ uint32_t smem_u32(const void* p) {
    return (uint32_t)__cvta_generic_to_shared(p);
}

static __device__ __forceinline__ void mma_bf16(
    float* d, const uint32_t* a, const uint32_t* b)
{
    asm volatile(
        "mma.sync.aligned.m16n8k16.row.col.f32.bf16.bf16.f32 "
        "{%0,%1,%2,%3}, {%4,%5,%6,%7}, {%8,%9}, {%0,%1,%2,%3};"
        : "+f"(d[0]), "+f"(d[1]), "+f"(d[2]), "+f"(d[3])
        : "r"(a[0]), "r"(a[1]), "r"(a[2]), "r"(a[3]), "r"(b[0]), "r"(b[1]));
}

static __device__ __forceinline__ void ldmatrix_x4(uint32_t* r, uint32_t addr)
{
    asm volatile("ldmatrix.sync.aligned.m8n8.x4.shared.b16 {%0,%1,%2,%3}, [%4];"
                 : "=r"(r[0]), "=r"(r[1]), "=r"(r[2]), "=r"(r[3]) : "r"(addr));
}

static __device__ __forceinline__ void ldmatrix_x2(uint32_t* r, uint32_t addr)
{
    asm volatile("ldmatrix.sync.aligned.m8n8.x2.shared.b16 {%0,%1}, [%2];"
                 : "=r"(r[0]), "=r"(r[1]) : "r"(addr));
}

static __device__ __forceinline__ void cp16(uint32_t dst, const void* src, int sz)
{
    asm volatile("cp.async.cg.shared.global [%0], [%1], 16, %2;"
                 :: "r"(dst), "l"(src), "r"(sz));
}

// ---------------------------------------------------------------------------
// bf16x3 GEMM via mma.sync:  C[M,N] = A[M,K] @ B[N,K]^T  (~fp32 accuracy)
// ---------------------------------------------------------------------------
#define ROWB   80
#define MATB   (128 * ROWB)
#define STAGEB (4 * MATB)
#define GEMM_SMEM (2 * STAGEB)

__global__ void __launch_bounds__(256) gemm_mma(
    const __nv_bfloat16* __restrict__ Ah, const __nv_bfloat16* __restrict__ Al,
    const __nv_bfloat16* __restrict__ Bh, const __nv_bfloat16* __restrict__ Bl,
    float* __restrict__ C, int M, int N, int K)
{
    extern __shared__ __align__(128) char smem[];
    const uint32_t sb = smem_u32(smem);
    const int tid = threadIdx.x;
    const int wid = tid >> 5, lid = tid & 31;
    const int bm = blockIdx.y * 128;
    const int bn = blockIdx.x * 128;
    const int wr = wid & 1;
    const int wc = wid >> 1;

    float acc[4][4][4];
#pragma unroll
    for (int i = 0; i < 4; i++)
#pragma unroll
        for (int j = 0; j < 4; j++)
#pragma unroll
            for (int k = 0; k < 4; k++) acc[i][j][k] = 0.f;

    const int lrow = tid >> 1;
    const int lch  = (tid & 1) * 2;
    const int bok  = (bn + lrow) < N ? 16 : 0;
    const size_t arowoff = (size_t)(bm + lrow) * K;
    const size_t browoff = (size_t)(bok ? (bn + lrow) : 0) * K;
    const uint32_t dst0 = sb + lrow * ROWB + lch * 16;

    const int NC = K >> 5;

    {
        const size_t ao = arowoff + lch * 8;
        const size_t bo = browoff + lch * 8;
        cp16(dst0,             Ah + ao, 16); cp16(dst0 + 16,            Ah + ao + 8, 16);
        cp16(dst0 + MATB,      Al + ao, 16); cp16(dst0 + MATB + 16,     Al + ao + 8, 16);
        cp16(dst0 + 2*MATB,    Bh + bo, bok); cp16(dst0 + 2*MATB + 16,  Bh + bo + 8, bok);
        cp16(dst0 + 3*MATB,    Bl + bo, bok); cp16(dst0 + 3*MATB + 16,  Bl + bo + 8, bok);
        asm volatile("cp.async.commit_group;");
    }

    for (int c = 0; c < NC; ++c) {
        if (c + 1 < NC) {
            const uint32_t d = dst0 + ((c + 1) & 1) * STAGEB;
            const size_t ao = arowoff + (size_t)(c + 1) * 32 + lch * 8;
            const size_t bo = browoff + (size_t)(c + 1) * 32 + lch * 8;
            cp16(d,            Ah + ao, 16); cp16(d + 16,           Ah + ao + 8, 16);
            cp16(d + MATB,     Al + ao, 16); cp16(d + MATB + 16,    Al + ao + 8, 16);
            cp16(d + 2*MATB,   Bh + bo, bok); cp16(d + 2*MATB + 16, Bh + bo + 8, bok);
            cp16(d + 3*MATB,   Bl + bo, bok); cp16(d + 3*MATB + 16, Bl + bo + 8, bok);
            asm volatile("cp.async.commit_group;");
            asm volatile("cp.async.wait_group 1;");
        } else {
            asm volatile("cp.async.wait_group 0;");
        }
        __syncthreads();

        const uint32_t st = sb + (c & 1) * STAGEB;
#pragma unroll
        for (int ks = 0; ks < 2; ++ks) {
            uint32_t ah[4][4], al[4][4], bh[4][2], bl[4][2];
            const int arow = wr * 64 + (lid & 15);
            const int akc  = ks * 2 + (lid >> 4);
#pragma unroll
            for (int mt = 0; mt < 4; ++mt) {
                const uint32_t a = st + (arow + mt * 16) * ROWB + akc * 16;
                ldmatrix_x4(ah[mt], a);
                ldmatrix_x4(al[mt], a + MATB);
            }
            const int brow = wc * 32 + (lid & 7);
            const int bkc  = ks * 2 + ((lid >> 3) & 1);
#pragma unroll
            for (int nt = 0; nt < 4; ++nt) {
                const uint32_t b = st + 2*MATB + (brow + nt * 8) * ROWB + bkc * 16;
                ldmatrix_x2(bh[nt], b);
                ldmatrix_x2(bl[nt], b + MATB);
            }
#pragma unroll
            for (int mt = 0; mt < 4; ++mt)
#pragma unroll
                for (int nt = 0; nt < 4; ++nt) {
                    mma_bf16(acc[mt][nt], ah[mt], bh[nt]);
                    mma_bf16(acc[mt][nt], ah[mt], bl[nt]);
                    mma_bf16(acc[mt][nt], al[mt], bh[nt]);
                }
        }
        __syncthreads();
    }

    const int mbase = bm + wr * 64 + (lid >> 2);
    const int nbase = bn + wc * 32 + (lid & 3) * 2;
#pragma unroll
    for (int mt = 0; mt < 4; ++mt) {
#pragma unroll
        for (int nt = 0; nt < 4; ++nt) {
            const int n0 = nbase + nt * 8;
            if (n0 < N) {
                const int m0 = mbase + mt * 16;
                float2 v0 = make_float2(acc[mt][nt][0], acc[mt][nt][1]);
                float2 v1 = make_float2(acc[mt][nt][2], acc[mt][nt][3]);
                *(float2*)(C + (size_t)m0 * N + n0)       = v0;
                *(float2*)(C + (size_t)(m0 + 8) * N + n0) = v1;
            }
        }
    }
}

// ---------------------------------------------------------------------------
// fp32 -> bf16 hi/lo split
// ---------------------------------------------------------------------------
__global__ void split_kernel(const float* __restrict__ src,
                             __nv_bfloat16* __restrict__ hi,
                             __nv_bfloat16* __restrict__ lo, int n)
{
    const int i = blockIdx.x * 256 + threadIdx.x;
    if (i >= n) return;
    const float x = src[i];
    const __nv_bfloat16 h = __float2bfloat16(x);
    hi[i] = h;
    lo[i] = __float2bfloat16(x - __bfloat162float(h));
}

// ---------------------------------------------------------------------------
// Depthwise causal conv (width 4) + bias + SiLU over the xBC slice of g_zx.
// ---------------------------------------------------------------------------
__global__ void conv_silu_kernel(const float* __restrict__ cw,
                                 const float* __restrict__ cb)
{
    const int idx = blockIdx.x * 256 + threadIdx.x;
    if (idx >= NTOK * CONVDIM) return;
    const int c  = idx % CONVDIM;
    const int bt = idx / CONVDIM;
    const int t  = bt % SEQLEN;
    float acc = cb[c];
#pragma unroll
    for (int k = 0; k < 4; k++) {
        const int tt = t - 3 + k;
        if (tt >= 0)
            acc = fmaf(cw[c * 4 + k],
                       g_zx[((size_t)bt + k - 3) * DINPROJ + DINNER + c], acc);
    }
    g_conv[idx] = acc / (1.f + __expf(-acc));
}

// ---------------------------------------------------------------------------
// dt_dis = softplus(dt + dt_bias); dA = exp(dt_dis * (-exp(A_log)))
// ---------------------------------------------------------------------------
__global__ void dt_kernel(const float* __restrict__ dt_bias,
                          const float* __restrict__ A_log)
{
    const int idx = blockIdx.x * 256 + threadIdx.x;
    if (idx >= NTOK * NHEADS) return;
    const int h  = idx % NHEADS;
    const int bt = idx / NHEADS;
    const float x  = g_zx[(size_t)bt * DINPROJ + DINNER + CONVDIM + h] + dt_bias[h];
    const float sp = (x > 20.f) ? x : log1pf(expf(x));
    const float Ah = -expf(A_log[h]);
    g_dt[idx] = sp;
    g_dA[idx] = expf(sp * Ah);
}

__global__ void zero_y_kernel()
{
    const int idx = blockIdx.x * 256 + threadIdx.x;
    if (idx < NTOK * DINNER) g_y[idx] = 0.f;
}

// ---------------------------------------------------------------------------
// Within-segment inclusive cumulative product of dA: one warp per (seg,h,b).
// ---------------------------------------------------------------------------
__global__ void cump_kernel()
{
    const int seg = blockIdx.x, h = blockIdx.y, b = blockIdx.z;
    const int lane = threadIdx.x;
    const size_t tbase = (size_t)b * SEQLEN + (size_t)seg * SEGLEN;
    const float* dAp = g_dA + tbase * NHEADS + h;
    float c[8];
    float run = 1.f;
#pragma unroll
    for (int i = 0; i < 8; i++) {
        run *= dAp[(size_t)(lane * 8 + i) * NHEADS];
        c[i] = run;
    }
    // inclusive scan (product) of per-lane totals
    float sc = run;
#pragma unroll
    for (int off = 1; off < 32; off <<= 1) {
        const float t = __shfl_up_sync(0xffffffffu, sc, off);
        if (lane >= off) sc *= t;
    }
    float excl = __shfl_up_sync(0xffffffffu, sc, 1);
    if (lane == 0) excl = 1.f;
    float* outp = g_cumP + tbase * NHEADS + h;
#pragma unroll
    for (int i = 0; i < 8; i++)
        outp[(size_t)(lane * 8 + i) * NHEADS] = excl * c[i];
}

// ---------------------------------------------------------------------------
// Phase-1 selective scan on one segment from zero state (4-deep prefetch).
// grid = (4 n-slices, NHEADS, NSEG*BATCH). Writes y_local (atomics) and the
// segment-final local state to g_fstate.
// ---------------------------------------------------------------------------
#define PF 4

__global__ __launch_bounds__(256) void scan_kernel()
{
    const int g4 = blockIdx.x, h = blockIdx.y;
    const int b = blockIdx.z & 1, seg = blockIdx.z >> 1;
    const int tid = threadIdx.x;
    const int p = tid >> 2, q = tid & 3;
    const int nb = g4 * 32 + q * 8;

    const size_t tbase = (size_t)b * SEQLEN + (size_t)seg * SEGLEN;
    const float* rowbase = g_conv + tbase * CONVDIM;
    const float* dtp = g_dt + tbase * NHEADS + h;
    const float* dAp = g_dA + tbase * NHEADS + h;
    float* yout = g_y + tbase * DINNER + h * HEADDIM + p;

    const int xoff = h * HEADDIM + p;

    float s[8];
#pragma unroll
    for (int i = 0; i < 8; i++) s[i] = 0.f;

    float4 pB0[PF], pB1[PF], pC0[PF], pC1[PF];
    float  px[PF], pdt[PF], pdA[PF];
#pragma unroll
    for (int i = 0; i < PF; i++) {
        const float* r = rowbase + (size_t)i * CONVDIM;
        pB0[i] = *(const float4*)(r + DINNER + nb);
        pB1[i] = *(const float4*)(r + DINNER + nb + 4);
        pC0[i] = *(const float4*)(r + DINNER + DSTATE + nb);
        pC1[i] = *(const float4*)(r + DINNER + DSTATE + nb + 4);
        px[i]  = r[xoff];
        pdt[i] = dtp[(size_t)i * NHEADS];
        pdA[i] = dAp[(size_t)i * NHEADS];
    }

    for (int t = 0; t < SEGLEN; t += PF) {
#pragma unroll
        for (int j = 0; j < PF; j++) {
            const float4 B0 = pB0[j], B1 = pB1[j], C0 = pC0[j], C1 = pC1[j];
            const float xv = px[j], dtv = pdt[j], dAv = pdA[j];

            const int tn = t + j + PF;
            if (tn < SEGLEN) {
                const float* r = rowbase + (size_t)tn * CONVDIM;
                pB0[j] = *(const float4*)(r + DINNER + nb);
                pB1[j] = *(const float4*)(r + DINNER + nb + 4);
                pC0[j] = *(const float4*)(r + DINNER + DSTATE + nb);
                pC1[j] = *(const float4*)(r + DINNER + DSTATE + nb + 4);
                px[j]  = r[xoff];
                pdt[j] = dtp[(size_t)tn * NHEADS];
                pdA[j] = dAp[(size_t)tn * NHEADS];
            }

            const float coef = dtv * xv;
            float acc;
            s[0] = fmaf(s[0], dAv, coef * B0.x); acc = s[0] * C0.x;
            s[1] = fmaf(s[1], dAv, coef * B0.y); acc = fmaf(s[1], C0.y, acc);
            s[2] = fmaf(s[2], dAv, coef * B0.z); acc = fmaf(s[2], C0.z, acc);
            s[3] = fmaf(s[3], dAv, coef * B0.w); acc = fmaf(s[3], C0.w, acc);
            s[4] = fmaf(s[4], dAv, coef * B1.x); acc = fmaf(s[4], C1.x, acc);
            s[5] = fmaf(s[5], dAv, coef * B1.y); acc = fmaf(s[5], C1.y, acc);
            s[6] = fmaf(s[6], dAv, coef * B1.z); acc = fmaf(s[6], C1.z, acc);
            s[7] = fmaf(s[7], dAv, coef * B1.w); acc = fmaf(s[7], C1.w, acc);
            acc += __shfl_xor_sync(0xffffffffu, acc, 1);
            acc += __shfl_xor_sync(0xffffffffu, acc, 2);
            if (q == 0) atomicAdd(yout + (size_t)(t + j) * DINNER, acc);
        }
    }

    // write segment-final local state
    float* fs = g_fstate + ((((size_t)seg * BATCH + b) * NHEADS + h) << 13)
              + (size_t)p * DSTATE + nb;
    *(float4*)fs       = make_float4(s[0], s[1], s[2], s[3]);
    *(float4*)(fs + 4) = make_float4(s[4], s[5], s[6], s[7]);
}

// ---------------------------------------------------------------------------
// Sequential combine over segments: S0[s] = S0[s-1]*P[s-1] + F[s-1].
// grid = (NHEADS, BATCH), 256 threads, each owns 32 state elements (float4 x8).
// ---------------------------------------------------------------------------
__global__ __launch_bounds__(256) void combine_kernel()
{
    const int h = blockIdx.x, b = blockIdx.y;
    const int tid = threadIdx.x;
    float4 acc[8];
#pragma unroll
    for (int r = 0; r < 8; r++) acc[r] = make_float4(0.f, 0.f, 0.f, 0.f);

    for (int s = 0; s < NSEG; ++s) {
        const size_t sb = (((size_t)s * BATCH + b) * NHEADS + h) << 13;
#pragma unroll
        for (int r = 0; r < 8; r++)
            *(float4*)(g_istate + sb + r * 1024 + tid * 4) = acc[r];
        const float P = g_cumP[((size_t)b * SEQLEN + (size_t)s * SEGLEN + SEGLEN - 1)
                               * NHEADS + h];
#pragma unroll
        for (int r = 0; r < 8; r++) {
            const float4 f = *(const float4*)(g_fstate + sb + r * 1024 + tid * 4);
            acc[r].x = fmaf(acc[r].x, P, f.x);
            acc[r].y = fmaf(acc[r].y, P, f.y);
            acc[r].z = fmaf(acc[r].z, P, f.z);
            acc[r].w = fmaf(acc[r].w, P, f.w);
        }
    }
}

// ---------------------------------------------------------------------------
// Correction: y[t,p] += cumP[t] * (C_t · S0_seg[p,:]).
// grid = (NSEG-1, NHEADS, BATCH), 256 threads.
// thread (p2 = tid>>3 in [0,32), q = tid&7): handles p2 and p2+32, n-slice q*16.
// S0 held in registers (8 float4).
// ---------------------------------------------------------------------------
__global__ __launch_bounds__(256) void correction_kernel()
{
    const int seg = blockIdx.x + 1, h = blockIdx.y, b = blockIdx.z;
    const int tid = threadIdx.x;
    const int q = tid & 7, p2 = tid >> 3;

    const size_t sb = (((size_t)seg * BATCH + b) * NHEADS + h) << 13;
    const float* s0a = g_istate + sb + (size_t)p2 * DSTATE + q * 16;
    const float* s0b = s0a + 32 * DSTATE;
    float4 SA[4], SB[4];
#pragma unroll
    for (int i = 0; i < 4; i++) {
        SA[i] = *(const float4*)(s0a + i * 4);
        SB[i] = *(const float4*)(s0b + i * 4);
    }

    const size_t t0 = (size_t)b * SEQLEN + (size_t)seg * SEGLEN;
#pragma unroll 2
    for (int t = 0; t < SEGLEN; ++t) {
        const float* crow = g_conv + (t0 + t) * CONVDIM + DINNER + DSTATE + q * 16;
        const float cp = g_cumP[(t0 + t) * NHEADS + h];
        float a0 = 0.f, a1 = 0.f;
#pragma unroll
        for (int i = 0; i < 4; i++) {
            const float4 c = *(const float4*)(crow + i * 4);
            a0 = fmaf(SA[i].x, c.x, a0); a0 = fmaf(SA[i].y, c.y, a0);
            a0 = fmaf(SA[i].z, c.z, a0); a0 = fmaf(SA[i].w, c.w, a0);
            a1 = fmaf(SB[i].x, c.x, a1); a1 = fmaf(SB[i].y, c.y, a1);
            a1 = fmaf(SB[i].z, c.z, a1); a1 = fmaf(SB[i].w, c.w, a1);
        }
        a0 += __shfl_xor_sync(0xffffffffu, a0, 1);
        a0 += __shfl_xor_sync(0xffffffffu, a0, 2);
        a0 += __shfl_xor_sync(0xffffffffu, a0, 4);
        a1 += __shfl_xor_sync(0xffffffffu, a1, 1);
        a1 += __shfl_xor_sync(0xffffffffu, a1, 2);
        a1 += __shfl_xor_sync(0xffffffffu, a1, 4);
        if (q == 0) {
            float* yp = g_y + (t0 + t) * DINNER + h * HEADDIM + p2;
            atomicAdd(yp,      cp * a0);
            atomicAdd(yp + 32, cp * a1);
        }
    }
}

// ---------------------------------------------------------------------------
// y += x*D; yz = y*silu(z); RMSNorm(yz) * norm_w  -> bf16 hi/lo (GEMM2 input)
// ---------------------------------------------------------------------------
__global__ __launch_bounds__(256) void gate_norm_kernel(
    const float* __restrict__ Dv, const float* __restrict__ nw)
{
    const int bt = blockIdx.x;
    const float* zrow = g_zx   + (size_t)bt * DINPROJ;
    const float* xrow = g_conv + (size_t)bt * CONVDIM;
    const float* yrow = g_y    + (size_t)bt * DINNER;

    float v[6];
    float ss = 0.f;
#pragma unroll
    for (int i = 0; i < 6; i++) {
        const int c = threadIdx.x + i * 256;
        const float yv = fmaf(xrow[c], Dv[c >> 6], yrow[c]);
        const float z  = zrow[c];
        const float gz = z / (1.f + __expf(-z));
        const float val = yv * gz;
        v[i] = val;
        ss = fmaf(val, val, ss);
    }
#pragma unroll
    for (int o = 16; o; o >>= 1) ss += __shfl_xor_sync(0xffffffffu, ss, o);
    __shared__ float sred[8];
    if ((threadIdx.x & 31) == 0) sred[threadIdx.x >> 5] = ss;
    __syncthreads();
    float tot = 0.f;
#pragma unroll
    for (int i = 0; i < 8; i++) tot += sred[i];
    const float scale = rsqrtf(tot * (1.f / DINNER) + 1e-5f);

    __nv_bfloat16* yh = g_yn_hi + (size_t)bt * DINNER;
    __nv_bfloat16* yl = g_yn_lo + (size_t)bt * DINNER;
#pragma unroll
    for (int i = 0; i < 6; i++) {
        const int c = threadIdx.x + i * 256;
        const float val = v[i] * scale * nw[c];
        const __nv_bfloat16 h = __float2bfloat16(val);
        yh[c] = h;
        yl[c] = __float2bfloat16(val - __bfloat162float(h));
    }
}

// ---------------------------------------------------------------------------
// Launch
// ---------------------------------------------------------------------------
extern "C" void kernel_launch(void* const* d_in, const int* in_sizes, int n_in,
                              void* d_out, int out_size)
{
    const float* u          = (const float*)d_in[0];
    const float* in_proj_w  = (const float*)d_in[1];
    const float* conv_w     = (const float*)d_in[2];
    const float* conv_b     = (const float*)d_in[3];
    const float* dt_bias    = (const float*)d_in[4];
    const float* A_log      = (const float*)d_in[5];
    const float* Dv         = (const float*)d_in[6];
    const float* norm_w     = (const float*)d_in[7];
    const float* out_proj_w = (const float*)d_in[8];
    float* out = (float*)d_out;

    float* zx = nullptr;
    __nv_bfloat16 *uh, *ul, *w1h, *w1l, *w2h, *w2l, *ynh, *ynl;
    cudaGetSymbolAddress((void**)&zx,  g_zx);
    cudaGetSymbolAddress((void**)&uh,  g_u_hi);
    cudaGetSymbolAddress((void**)&ul,  g_u_lo);
    cudaGetSymbolAddress((void**)&w1h, g_w1_hi);
    cudaGetSymbolAddress((void**)&w1l, g_w1_lo);
    cudaGetSymbolAddress((void**)&w2h, g_w2_hi);
    cudaGetSymbolAddress((void**)&w2l, g_w2_lo);
    cudaGetSymbolAddress((void**)&ynh, g_yn_hi);
    cudaGetSymbolAddress((void**)&ynl, g_yn_lo);

    cudaFuncSetAttribute(gemm_mma,
                         cudaFuncAttributeMaxDynamicSharedMemorySize, GEMM_SMEM);

    // 0) bf16 hi/lo splits
    split_kernel<<<(NTOK * DMODEL + 255) / 256, 256>>>(u, uh, ul, NTOK * DMODEL);
    split_kernel<<<(DINPROJ * DMODEL + 255) / 256, 256>>>(in_proj_w, w1h, w1l,
                                                          DINPROJ * DMODEL);
    split_kernel<<<(DMODEL * DINNER + 255) / 256, 256>>>(out_proj_w, w2h, w2l,
                                                         DMODEL * DINNER);

    // 1) zxbcdt = u @ in_proj_w^T — HMMA bf16x3
    dim3 g1((DINPROJ + 127) / 128, NTOK / 128);
    gemm_mma<<<g1, 256, GEMM_SMEM>>>(uh, ul, w1h, w1l, zx,
                                     NTOK, DINPROJ, DMODEL);

    // 2) depthwise causal conv + silu
    conv_silu_kernel<<<(NTOK * CONVDIM + 255) / 256, 256>>>(conv_w, conv_b);

    // 3) dt softplus / dA
    dt_kernel<<<(NTOK * NHEADS + 255) / 256, 256>>>(dt_bias, A_log);

    // 4) zero scan accumulator; cumP prefix products
    zero_y_kernel<<<(NTOK * DINNER + 255) / 256, 256>>>();
    cump_kernel<<<dim3(NSEG, NHEADS, BATCH), 32>>>();

    // 5) segmented selective scan
    scan_kernel<<<dim3(4, NHEADS, NSEG * BATCH), 256>>>();

    // 6) combine segment states, then cross-segment correction
    combine_kernel<<<dim3(NHEADS, BATCH), 256>>>();
    correction_kernel<<<dim3(NSEG - 1, NHEADS, BATCH), 256>>>();

    // 7) gate + RMSNorm -> bf16 hi/lo
    gate_norm_kernel<<<NTOK, 256>>>(Dv, norm_w);

    // 8) out = yn @ out_proj_w^T — HMMA bf16x3
    dim3 g2((DMODEL + 127) / 128, NTOK / 128);
    gemm_mma<<<g2, 256, GEMM_SMEM>>>(ynh, ynl, w2h, w2l, out,
                                     NTOK, DMODEL, DINNER);
}

// round 6
// speedup vs baseline: 1.0644x; 1.0644x over previous
#include <cuda_runtime.h>
#include <cuda_bf16.h>
#include <math.h>
#include <stdint.h>

#define BATCH   2
#define SEQLEN  2048
#define NTOK    (BATCH*SEQLEN)        // 4096
#define DMODEL  768
#define DINNER  1536
#define DSTATE  128
#define HEADDIM 64
#define NHEADS  24
#define CONVDIM 1792                  // DINNER + 2*DSTATE
#define DINPROJ 3352                  // 2*DINNER + 2*DSTATE + NHEADS

// ---------------------------------------------------------------------------
// Scratch buffers (device globals — no allocations allowed)
// ---------------------------------------------------------------------------
__device__ __align__(128) float g_zx[NTOK * DINPROJ];     // in_proj output
__device__ __align__(128) float g_conv[NTOK * CONVDIM];   // conv+silu output (x | B | C)
__device__ __align__(128) float g_dt[NTOK * NHEADS];      // softplus(dt + bias)
__device__ __align__(128) float g_dA[NTOK * NHEADS];      // exp(dt * A)
__device__ __align__(128) float g_y[NTOK * DINNER];       // scan output (atomics)

// bf16 hi/lo split operands for tensor-core GEMMs
__device__ __align__(128) __nv_bfloat16 g_u_hi[NTOK * DMODEL];
__device__ __align__(128) __nv_bfloat16 g_u_lo[NTOK * DMODEL];
__device__ __align__(128) __nv_bfloat16 g_w1_hi[DINPROJ * DMODEL];
__device__ __align__(128) __nv_bfloat16 g_w1_lo[DINPROJ * DMODEL];
__device__ __align__(128) __nv_bfloat16 g_w2_hi[DMODEL * DINNER];
__device__ __align__(128) __nv_bfloat16 g_w2_lo[DMODEL * DINNER];
__device__ __align__(128) __nv_bfloat16 g_yn_hi[NTOK * DINNER];
__device__ __align__(128) __nv_bfloat16 g_yn_lo[NTOK * DINNER];

// ---------------------------------------------------------------------------
// MMA helpers (baseline PTX — works under compute_103 virtual arch)
// ---------------------------------------------------------------------------
static __device__ __forceinline__ uint32_t smem_u32(const void* p) {
    return (uint32_t)__cvta_generic_to_shared(p);
}

static __device__ __forceinline__ void mma_bf16(
    float* d, const uint32_t* a, const uint32_t* b)
{
    asm volatile(
        "mma.sync.aligned.m16n8k16.row.col.f32.bf16.bf16.f32 "
        "{%0,%1,%2,%3}, {%4,%5,%6,%7}, {%8,%9}, {%0,%1,%2,%3};"
        : "+f"(d[0]), "+f"(d[1]), "+f"(d[2]), "+f"(d[3])
        : "r"(a[0]), "r"(a[1]), "r"(a[2]), "r"(a[3]), "r"(b[0]), "r"(b[1]));
}

static __device__ __forceinline__ void ldmatrix_x4(uint32_t* r, uint32_t addr)
{
    asm volatile("ldmatrix.sync.aligned.m8n8.x4.shared.b16 {%0,%1,%2,%3}, [%4];"
                 : "=r"(r[0]), "=r"(r[1]), "=r"(r[2]), "=r"(r[3]) : "r"(addr));
}

static __device__ __forceinline__ void ldmatrix_x2(uint32_t* r, uint32_t addr)
{
    asm volatile("ldmatrix.sync.aligned.m8n8.x2.shared.b16 {%0,%1}, [%2];"
                 : "=r"(r[0]), "=r"(r[1]) : "r"(addr));
}

static __device__ __forceinline__ void cp16(uint32_t dst, const void* src, int sz)
{
    asm volatile("cp.async.cg.shared.global [%0], [%1], 16, %2;"
                 :: "r"(dst), "l"(src), "r"(sz));
}

// ---------------------------------------------------------------------------
// bf16x3 GEMM via mma.sync:  C[M,N] = A[M,K] @ B[N,K]^T  (~fp32 accuracy)
// CTA tile 256x128, BK=32, 16 warps (4x4), warp tile 64x32, 512 threads.
// Double-buffered cp.async staging; 80B-padded rows -> conflict-free ldmatrix.
// M % 256 == 0, K % 32 == 0; N guarded.
// Staging-op economy: (256+128)*32 elems per chunk for a 256x128 output tile
// (1.67x fewer LDGSTS per output element than 128x128 tiles).
// ---------------------------------------------------------------------------
#define ROWB   80                          // padded row stride (32 bf16 -> 80B)
#define AMATB  (256 * ROWB)                // 20480 per A matrix (hi or lo)
#define BMATB  (128 * ROWB)                // 10240 per B matrix
#define STAGEB (2 * AMATB + 2 * BMATB)     // 61440
#define GEMM_SMEM (2 * STAGEB)             // 122880

__global__ void __launch_bounds__(512, 1) gemm_mma(
    const __nv_bfloat16* __restrict__ Ah, const __nv_bfloat16* __restrict__ Al,
    const __nv_bfloat16* __restrict__ Bh, const __nv_bfloat16* __restrict__ Bl,
    float* __restrict__ C, int M, int N, int K)
{
    extern __shared__ __align__(128) char smem[];
    const uint32_t sb = smem_u32(smem);
    const int tid = threadIdx.x;
    const int wid = tid >> 5, lid = tid & 31;
    const int bm = blockIdx.y * 256;
    const int bn = blockIdx.x * 128;
    const int wr = wid & 3;               // warp m-row (x64)
    const int wc = wid >> 2;              // warp n-col (x32)

    float acc[4][4][4];
#pragma unroll
    for (int i = 0; i < 4; i++)
#pragma unroll
        for (int j = 0; j < 4; j++)
#pragma unroll
            for (int k = 0; k < 4; k++) acc[i][j][k] = 0.f;

    // A staging: row = tid>>1 (0..255), chunks (tid&1)*2, +1   (2 cp16 per mat)
    const int alrow = tid >> 1;
    const int alch  = (tid & 1) * 2;
    const size_t arowoff = (size_t)(bm + alrow) * K;
    const uint32_t adst0 = sb + alrow * ROWB + alch * 16;
    // B staging: row = tid>>2 (0..127), chunk tid&3             (1 cp16 per mat)
    const int blrow = tid >> 2;
    const int blch  = tid & 3;
    const int bok   = (bn + blrow) < N ? 16 : 0;
    const size_t browoff = (size_t)(bok ? (bn + blrow) : 0) * K;
    const uint32_t bdst0 = sb + 2 * AMATB + blrow * ROWB + blch * 16;

    const int NC = K >> 5;

    // prologue: stage chunk 0 into stage 0
    {
        const size_t ao = arowoff + alch * 8;
        const size_t bo = browoff + blch * 8;
        cp16(adst0,              Ah + ao, 16); cp16(adst0 + 16,         Ah + ao + 8, 16);
        cp16(adst0 + AMATB,      Al + ao, 16); cp16(adst0 + AMATB + 16, Al + ao + 8, 16);
        cp16(bdst0,              Bh + bo, bok);
        cp16(bdst0 + BMATB,      Bl + bo, bok);
        asm volatile("cp.async.commit_group;");
    }

    for (int c = 0; c < NC; ++c) {
        if (c + 1 < NC) {
            const uint32_t stoff = ((c + 1) & 1) * STAGEB;
            const size_t ao = arowoff + (size_t)(c + 1) * 32 + alch * 8;
            const size_t bo = browoff + (size_t)(c + 1) * 32 + blch * 8;
            const uint32_t ad = adst0 + stoff;
            const uint32_t bd = bdst0 + stoff;
            cp16(ad,              Ah + ao, 16); cp16(ad + 16,         Ah + ao + 8, 16);
            cp16(ad + AMATB,      Al + ao, 16); cp16(ad + AMATB + 16, Al + ao + 8, 16);
            cp16(bd,              Bh + bo, bok);
            cp16(bd + BMATB,      Bl + bo, bok);
            asm volatile("cp.async.commit_group;");
            asm volatile("cp.async.wait_group 1;");
        } else {
            asm volatile("cp.async.wait_group 0;");
        }
        __syncthreads();

        const uint32_t st = sb + (c & 1) * STAGEB;
#pragma unroll
        for (int ks = 0; ks < 2; ++ks) {
            uint32_t ah[4][4], al[4][4], bh[4][2], bl[4][2];
            const int arow = wr * 64 + (lid & 15);
            const int akc  = ks * 2 + (lid >> 4);
#pragma unroll
            for (int mt = 0; mt < 4; ++mt) {
                const uint32_t a = st + (arow + mt * 16) * ROWB + akc * 16;
                ldmatrix_x4(ah[mt], a);
                ldmatrix_x4(al[mt], a + AMATB);
            }
            const int brow = wc * 32 + (lid & 7);
            const int bkc  = ks * 2 + ((lid >> 3) & 1);
#pragma unroll
            for (int nt = 0; nt < 4; ++nt) {
                const uint32_t b = st + 2 * AMATB + (brow + nt * 8) * ROWB + bkc * 16;
                ldmatrix_x2(bh[nt], b);
                ldmatrix_x2(bl[nt], b + BMATB);
            }
#pragma unroll
            for (int mt = 0; mt < 4; ++mt)
#pragma unroll
                for (int nt = 0; nt < 4; ++nt) {
                    mma_bf16(acc[mt][nt], ah[mt], bh[nt]);
                    mma_bf16(acc[mt][nt], ah[mt], bl[nt]);
                    mma_bf16(acc[mt][nt], al[mt], bh[nt]);
                }
        }
        __syncthreads();
    }

    // epilogue: fragment -> global (float2 pairs; N is even)
    const int mbase = bm + wr * 64 + (lid >> 2);
    const int nbase = bn + wc * 32 + (lid & 3) * 2;
#pragma unroll
    for (int mt = 0; mt < 4; ++mt) {
#pragma unroll
        for (int nt = 0; nt < 4; ++nt) {
            const int n0 = nbase + nt * 8;
            if (n0 < N) {
                const int m0 = mbase + mt * 16;
                float2 v0 = make_float2(acc[mt][nt][0], acc[mt][nt][1]);
                float2 v1 = make_float2(acc[mt][nt][2], acc[mt][nt][3]);
                *(float2*)(C + (size_t)m0 * N + n0)       = v0;
                *(float2*)(C + (size_t)(m0 + 8) * N + n0) = v1;
            }
        }
    }
}

// ---------------------------------------------------------------------------
// fp32 -> bf16 hi/lo split
// ---------------------------------------------------------------------------
__global__ void split_kernel(const float* __restrict__ src,
                             __nv_bfloat16* __restrict__ hi,
                             __nv_bfloat16* __restrict__ lo, int n)
{
    const int i = blockIdx.x * 256 + threadIdx.x;
    if (i >= n) return;
    const float x = src[i];
    const __nv_bfloat16 h = __float2bfloat16(x);
    hi[i] = h;
    lo[i] = __float2bfloat16(x - __bfloat162float(h));
}

// ---------------------------------------------------------------------------
// Depthwise causal conv (width 4) + bias + SiLU over the xBC slice of g_zx.
// ---------------------------------------------------------------------------
__global__ void conv_silu_kernel(const float* __restrict__ cw,
                                 const float* __restrict__ cb)
{
    const int idx = blockIdx.x * 256 + threadIdx.x;
    if (idx >= NTOK * CONVDIM) return;
    const int c  = idx % CONVDIM;
    const int bt = idx / CONVDIM;
    const int t  = bt % SEQLEN;
    float acc = cb[c];
#pragma unroll
    for (int k = 0; k < 4; k++) {
        const int tt = t - 3 + k;
        if (tt >= 0)
            acc = fmaf(cw[c * 4 + k],
                       g_zx[((size_t)bt + k - 3) * DINPROJ + DINNER + c], acc);
    }
    g_conv[idx] = acc / (1.f + __expf(-acc));   // silu
}

// ---------------------------------------------------------------------------
// dt_dis = softplus(dt + dt_bias); dA = exp(dt_dis * (-exp(A_log)))
// (precise expf: dA errors compound multiplicatively over the scan)
// ---------------------------------------------------------------------------
__global__ void dt_kernel(const float* __restrict__ dt_bias,
                          const float* __restrict__ A_log)
{
    const int idx = blockIdx.x * 256 + threadIdx.x;
    if (idx >= NTOK * NHEADS) return;
    const int h  = idx % NHEADS;
    const int bt = idx / NHEADS;
    const float x  = g_zx[(size_t)bt * DINPROJ + DINNER + CONVDIM + h] + dt_bias[h];
    const float sp = (x > 20.f) ? x : log1pf(expf(x));
    const float Ah = -expf(A_log[h]);
    g_dt[idx] = sp;
    g_dA[idx] = expf(sp * Ah);
}

__global__ void zero_y_kernel()
{
    const int idx = blockIdx.x * 256 + threadIdx.x;
    if (idx < NTOK * DINNER) g_y[idx] = 0.f;
}

// ---------------------------------------------------------------------------
// Selective scan with 4-deep register prefetch pipeline (R4 proven form).
// grid = (4 n-slices, NHEADS, BATCH), 256 threads.
// thread (p = tid>>2, q = tid&3) owns state[p, nb..nb+8) in registers.
// ---------------------------------------------------------------------------
#define PF 4

__global__ __launch_bounds__(256) void scan_kernel()
{
    const int g4 = blockIdx.x, h = blockIdx.y, b = blockIdx.z;
    const int tid = threadIdx.x;
    const int p = tid >> 2, q = tid & 3;
    const int nb = g4 * 32 + q * 8;

    const float* rowbase = g_conv + (size_t)b * SEQLEN * CONVDIM;
    const float* dtp = g_dt + (size_t)b * SEQLEN * NHEADS + h;
    const float* dAp = g_dA + (size_t)b * SEQLEN * NHEADS + h;
    float* yout = g_y + (size_t)b * SEQLEN * DINNER + h * HEADDIM + p;

    const int xoff = h * HEADDIM + p;

    float s[8];
#pragma unroll
    for (int i = 0; i < 8; i++) s[i] = 0.f;

    float4 pB0[PF], pB1[PF], pC0[PF], pC1[PF];
    float  px[PF], pdt[PF], pdA[PF];
#pragma unroll
    for (int i = 0; i < PF; i++) {
        const float* r = rowbase + (size_t)i * CONVDIM;
        pB0[i] = *(const float4*)(r + DINNER + nb);
        pB1[i] = *(const float4*)(r + DINNER + nb + 4);
        pC0[i] = *(const float4*)(r + DINNER + DSTATE + nb);
        pC1[i] = *(const float4*)(r + DINNER + DSTATE + nb + 4);
        px[i]  = r[xoff];
        pdt[i] = dtp[(size_t)i * NHEADS];
        pdA[i] = dAp[(size_t)i * NHEADS];
    }

    for (int t = 0; t < SEQLEN; t += PF) {
#pragma unroll
        for (int j = 0; j < PF; j++) {
            const float4 B0 = pB0[j], B1 = pB1[j], C0 = pC0[j], C1 = pC1[j];
            const float xv = px[j], dtv = pdt[j], dAv = pdA[j];

            const int tn = t + j + PF;
            if (tn < SEQLEN) {
                const float* r = rowbase + (size_t)tn * CONVDIM;
                pB0[j] = *(const float4*)(r + DINNER + nb);
                pB1[j] = *(const float4*)(r + DINNER + nb + 4);
                pC0[j] = *(const float4*)(r + DINNER + DSTATE + nb);
                pC1[j] = *(const float4*)(r + DINNER + DSTATE + nb + 4);
                px[j]  = r[xoff];
                pdt[j] = dtp[(size_t)tn * NHEADS];
                pdA[j] = dAp[(size_t)tn * NHEADS];
            }

            const float coef = dtv * xv;
            float acc;
            s[0] = fmaf(s[0], dAv, coef * B0.x); acc = s[0] * C0.x;
            s[1] = fmaf(s[1], dAv, coef * B0.y); acc = fmaf(s[1], C0.y, acc);
            s[2] = fmaf(s[2], dAv, coef * B0.z); acc = fmaf(s[2], C0.z, acc);
            s[3] = fmaf(s[3], dAv, coef * B0.w); acc = fmaf(s[3], C0.w, acc);
            s[4] = fmaf(s[4], dAv, coef * B1.x); acc = fmaf(s[4], C1.x, acc);
            s[5] = fmaf(s[5], dAv, coef * B1.y); acc = fmaf(s[5], C1.y, acc);
            s[6] = fmaf(s[6], dAv, coef * B1.z); acc = fmaf(s[6], C1.z, acc);
            s[7] = fmaf(s[7], dAv, coef * B1.w); acc = fmaf(s[7], C1.w, acc);
            acc += __shfl_xor_sync(0xffffffffu, acc, 1);
            acc += __shfl_xor_sync(0xffffffffu, acc, 2);
            if (q == 0) atomicAdd(yout + (size_t)(t + j) * DINNER, acc);
        }
    }
}

// ---------------------------------------------------------------------------
// y += x*D; yz = y*silu(z); RMSNorm(yz) * norm_w  -> bf16 hi/lo (GEMM2 input)
// ---------------------------------------------------------------------------
__global__ __launch_bounds__(256) void gate_norm_kernel(
    const float* __restrict__ Dv, const float* __restrict__ nw)
{
    const int bt = blockIdx.x;
    const float* zrow = g_zx   + (size_t)bt * DINPROJ;
    const float* xrow = g_conv + (size_t)bt * CONVDIM;
    const float* yrow = g_y    + (size_t)bt * DINNER;

    float v[6];
    float ss = 0.f;
#pragma unroll
    for (int i = 0; i < 6; i++) {
        const int c = threadIdx.x + i * 256;
        const float yv = fmaf(xrow[c], Dv[c >> 6], yrow[c]);
        const float z  = zrow[c];
        const float gz = z / (1.f + __expf(-z));
        const float val = yv * gz;
        v[i] = val;
        ss = fmaf(val, val, ss);
    }
#pragma unroll
    for (int o = 16; o; o >>= 1) ss += __shfl_xor_sync(0xffffffffu, ss, o);
    __shared__ float sred[8];
    if ((threadIdx.x & 31) == 0) sred[threadIdx.x >> 5] = ss;
    __syncthreads();
    float tot = 0.f;
#pragma unroll
    for (int i = 0; i < 8; i++) tot += sred[i];
    const float scale = rsqrtf(tot * (1.f / DINNER) + 1e-5f);

    __nv_bfloat16* yh = g_yn_hi + (size_t)bt * DINNER;
    __nv_bfloat16* yl = g_yn_lo + (size_t)bt * DINNER;
#pragma unroll
    for (int i = 0; i < 6; i++) {
        const int c = threadIdx.x + i * 256;
        const float val = v[i] * scale * nw[c];
        const __nv_bfloat16 h = __float2bfloat16(val);
        yh[c] = h;
        yl[c] = __float2bfloat16(val - __bfloat162float(h));
    }
}

// ---------------------------------------------------------------------------
// Launch
// ---------------------------------------------------------------------------
extern "C" void kernel_launch(void* const* d_in, const int* in_sizes, int n_in,
                              void* d_out, int out_size)
{
    const float* u          = (const float*)d_in[0];
    const float* in_proj_w  = (const float*)d_in[1];
    const float* conv_w     = (const float*)d_in[2];
    const float* conv_b     = (const float*)d_in[3];
    const float* dt_bias    = (const float*)d_in[4];
    const float* A_log      = (const float*)d_in[5];
    const float* Dv         = (const float*)d_in[6];
    const float* norm_w     = (const float*)d_in[7];
    const float* out_proj_w = (const float*)d_in[8];
    float* out = (float*)d_out;

    float* zx = nullptr;
    __nv_bfloat16 *uh, *ul, *w1h, *w1l, *w2h, *w2l, *ynh, *ynl;
    cudaGetSymbolAddress((void**)&zx,  g_zx);
    cudaGetSymbolAddress((void**)&uh,  g_u_hi);
    cudaGetSymbolAddress((void**)&ul,  g_u_lo);
    cudaGetSymbolAddress((void**)&w1h, g_w1_hi);
    cudaGetSymbolAddress((void**)&w1l, g_w1_lo);
    cudaGetSymbolAddress((void**)&w2h, g_w2_hi);
    cudaGetSymbolAddress((void**)&w2l, g_w2_lo);
    cudaGetSymbolAddress((void**)&ynh, g_yn_hi);
    cudaGetSymbolAddress((void**)&ynl, g_yn_lo);

    cudaFuncSetAttribute(gemm_mma,
                         cudaFuncAttributeMaxDynamicSharedMemorySize, GEMM_SMEM);

    // 0) bf16 hi/lo splits for GEMM operands
    split_kernel<<<(NTOK * DMODEL + 255) / 256, 256>>>(u, uh, ul, NTOK * DMODEL);
    split_kernel<<<(DINPROJ * DMODEL + 255) / 256, 256>>>(in_proj_w, w1h, w1l,
                                                          DINPROJ * DMODEL);
    split_kernel<<<(DMODEL * DINNER + 255) / 256, 256>>>(out_proj_w, w2h, w2l,
                                                         DMODEL * DINNER);

    // 1) zxbcdt = u @ in_proj_w^T   (4096 x 3352, K=768) — HMMA bf16x3
    dim3 g1((DINPROJ + 127) / 128, NTOK / 256);
    gemm_mma<<<g1, 512, GEMM_SMEM>>>(uh, ul, w1h, w1l, zx,
                                     NTOK, DINPROJ, DMODEL);

    // 2) depthwise causal conv + silu on xBC slice
    conv_silu_kernel<<<(NTOK * CONVDIM + 255) / 256, 256>>>(conv_w, conv_b);

    // 3) dt softplus / dA
    dt_kernel<<<(NTOK * NHEADS + 255) / 256, 256>>>(dt_bias, A_log);

    // 4) zero scan accumulator
    zero_y_kernel<<<(NTOK * DINNER + 255) / 256, 256>>>();

    // 5) selective scan (4-deep prefetch)
    scan_kernel<<<dim3(4, NHEADS, BATCH), 256>>>();

    // 6) gate + RMSNorm -> bf16 hi/lo
    gate_norm_kernel<<<NTOK, 256>>>(Dv, norm_w);

    // 7) out = yn @ out_proj_w^T   (4096 x 768, K=1536) — HMMA bf16x3
    dim3 g2((DMODEL + 127) / 128, NTOK / 256);
    gemm_mma<<<g2, 512, GEMM_SMEM>>>(ynh, ynl, w2h, w2l, out,
                                     NTOK, DMODEL, DINNER);
}

// round 7
// speedup vs baseline: 1.1328x; 1.0643x over previous
#include <cuda_runtime.h>
#include <cuda_bf16.h>
#include <math.h>
#include <stdint.h>

#define BATCH   2
#define SEQLEN  2048
#define NTOK    (BATCH*SEQLEN)        // 4096
#define DMODEL  768
#define DINNER  1536
#define DSTATE  128
#define HEADDIM 64
#define NHEADS  24
#define CONVDIM 1792                  // DINNER + 2*DSTATE
#define DINPROJ 3352                  // 2*DINNER + 2*DSTATE + NHEADS

// ---------------------------------------------------------------------------
// Scratch buffers (device globals — no allocations allowed)
// ---------------------------------------------------------------------------
__device__ __align__(128) float g_zx[NTOK * DINPROJ];     // in_proj output
__device__ __align__(128) float g_conv[NTOK * CONVDIM];   // conv+silu output (x | B | C)
__device__ __align__(128) float g_dt[NTOK * NHEADS];      // softplus(dt + bias)
__device__ __align__(128) float g_dA[NTOK * NHEADS];      // exp(dt * A)
__device__ __align__(128) float g_y[NTOK * DINNER];       // scan output (atomics)

// bf16 hi/lo split operands for tensor-core GEMMs
__device__ __align__(128) __nv_bfloat16 g_u_hi[NTOK * DMODEL];
__device__ __align__(128) __nv_bfloat16 g_u_lo[NTOK * DMODEL];
__device__ __align__(128) __nv_bfloat16 g_w1_hi[DINPROJ * DMODEL];
__device__ __align__(128) __nv_bfloat16 g_w1_lo[DINPROJ * DMODEL];
__device__ __align__(128) __nv_bfloat16 g_w2_hi[DMODEL * DINNER];
__device__ __align__(128) __nv_bfloat16 g_w2_lo[DMODEL * DINNER];
__device__ __align__(128) __nv_bfloat16 g_yn_hi[NTOK * DINNER];
__device__ __align__(128) __nv_bfloat16 g_yn_lo[NTOK * DINNER];

// ---------------------------------------------------------------------------
// MMA helpers (baseline PTX — works under compute_103 virtual arch)
// ---------------------------------------------------------------------------
static __device__ __forceinline__ uint32_t smem_u32(const void* p) {
    return (uint32_t)__cvta_generic_to_shared(p);
}

static __device__ __forceinline__ void mma_bf16(
    float* d, const uint32_t* a, const uint32_t* b)
{
    asm volatile(
        "mma.sync.aligned.m16n8k16.row.col.f32.bf16.bf16.f32 "
        "{%0,%1,%2,%3}, {%4,%5,%6,%7}, {%8,%9}, {%0,%1,%2,%3};"
        : "+f"(d[0]), "+f"(d[1]), "+f"(d[2]), "+f"(d[3])
        : "r"(a[0]), "r"(a[1]), "r"(a[2]), "r"(a[3]), "r"(b[0]), "r"(b[1]));
}

static __device__ __forceinline__ void ldmatrix_x4(uint32_t* r, uint32_t addr)
{
    asm volatile("ldmatrix.sync.aligned.m8n8.x4.shared.b16 {%0,%1,%2,%3}, [%4];"
                 : "=r"(r[0]), "=r"(r[1]), "=r"(r[2]), "=r"(r[3]) : "r"(addr));
}

static __device__ __forceinline__ void ldmatrix_x2(uint32_t* r, uint32_t addr)
{
    asm volatile("ldmatrix.sync.aligned.m8n8.x2.shared.b16 {%0,%1}, [%2];"
                 : "=r"(r[0]), "=r"(r[1]) : "r"(addr));
}

static __device__ __forceinline__ void cp16(uint32_t dst, const void* src, int sz)
{
    asm volatile("cp.async.cg.shared.global [%0], [%1], 16, %2;"
                 :: "r"(dst), "l"(src), "r"(sz));
}

// ---------------------------------------------------------------------------
// bf16x3 GEMM via mma.sync:  C[M,N] = A[M,K] @ B[N,K]^T  (~fp32 accuracy)
// CTA tile 128x128, BK=32, 8 warps (2x4), warp tile 64x32 (R4 proven form).
// ---------------------------------------------------------------------------
#define ROWB   80                         // padded row stride (32 bf16 -> 80B)
#define MATB   (128 * ROWB)               // 10240 per matrix
#define STAGEB (4 * MATB)                 // Ah | Al | Bh | Bl  = 40960
#define GEMM_SMEM (2 * STAGEB)            // 81920

__global__ void __launch_bounds__(256) gemm_mma(
    const __nv_bfloat16* __restrict__ Ah, const __nv_bfloat16* __restrict__ Al,
    const __nv_bfloat16* __restrict__ Bh, const __nv_bfloat16* __restrict__ Bl,
    float* __restrict__ C, int M, int N, int K)
{
    extern __shared__ __align__(128) char smem[];
    const uint32_t sb = smem_u32(smem);
    const int tid = threadIdx.x;
    const int wid = tid >> 5, lid = tid & 31;
    const int bm = blockIdx.y * 128;
    const int bn = blockIdx.x * 128;
    const int wr = wid & 1;
    const int wc = wid >> 1;

    float acc[4][4][4];
#pragma unroll
    for (int i = 0; i < 4; i++)
#pragma unroll
        for (int j = 0; j < 4; j++)
#pragma unroll
            for (int k = 0; k < 4; k++) acc[i][j][k] = 0.f;

    const int lrow = tid >> 1;
    const int lch  = (tid & 1) * 2;
    const int bok  = (bn + lrow) < N ? 16 : 0;
    const size_t arowoff = (size_t)(bm + lrow) * K;
    const size_t browoff = (size_t)(bok ? (bn + lrow) : 0) * K;
    const uint32_t dst0 = sb + lrow * ROWB + lch * 16;

    const int NC = K >> 5;

    {
        const size_t ao = arowoff + lch * 8;
        const size_t bo = browoff + lch * 8;
        cp16(dst0,             Ah + ao, 16); cp16(dst0 + 16,            Ah + ao + 8, 16);
        cp16(dst0 + MATB,      Al + ao, 16); cp16(dst0 + MATB + 16,     Al + ao + 8, 16);
        cp16(dst0 + 2*MATB,    Bh + bo, bok); cp16(dst0 + 2*MATB + 16,  Bh + bo + 8, bok);
        cp16(dst0 + 3*MATB,    Bl + bo, bok); cp16(dst0 + 3*MATB + 16,  Bl + bo + 8, bok);
        asm volatile("cp.async.commit_group;");
    }

    for (int c = 0; c < NC; ++c) {
        if (c + 1 < NC) {
            const uint32_t d = dst0 + ((c + 1) & 1) * STAGEB;
            const size_t ao = arowoff + (size_t)(c + 1) * 32 + lch * 8;
            const size_t bo = browoff + (size_t)(c + 1) * 32 + lch * 8;
            cp16(d,            Ah + ao, 16); cp16(d + 16,           Ah + ao + 8, 16);
            cp16(d + MATB,     Al + ao, 16); cp16(d + MATB + 16,    Al + ao + 8, 16);
            cp16(d + 2*MATB,   Bh + bo, bok); cp16(d + 2*MATB + 16, Bh + bo + 8, bok);
            cp16(d + 3*MATB,   Bl + bo, bok); cp16(d + 3*MATB + 16, Bl + bo + 8, bok);
            asm volatile("cp.async.commit_group;");
            asm volatile("cp.async.wait_group 1;");
        } else {
            asm volatile("cp.async.wait_group 0;");
        }
        __syncthreads();

        const uint32_t st = sb + (c & 1) * STAGEB;
#pragma unroll
        for (int ks = 0; ks < 2; ++ks) {
            uint32_t ah[4][4], al[4][4], bh[4][2], bl[4][2];
            const int arow = wr * 64 + (lid & 15);
            const int akc  = ks * 2 + (lid >> 4);
#pragma unroll
            for (int mt = 0; mt < 4; ++mt) {
                const uint32_t a = st + (arow + mt * 16) * ROWB + akc * 16;
                ldmatrix_x4(ah[mt], a);
                ldmatrix_x4(al[mt], a + MATB);
            }
            const int brow = wc * 32 + (lid & 7);
            const int bkc  = ks * 2 + ((lid >> 3) & 1);
#pragma unroll
            for (int nt = 0; nt < 4; ++nt) {
                const uint32_t b = st + 2*MATB + (brow + nt * 8) * ROWB + bkc * 16;
                ldmatrix_x2(bh[nt], b);
                ldmatrix_x2(bl[nt], b + MATB);
            }
#pragma unroll
            for (int mt = 0; mt < 4; ++mt)
#pragma unroll
                for (int nt = 0; nt < 4; ++nt) {
                    mma_bf16(acc[mt][nt], ah[mt], bh[nt]);
                    mma_bf16(acc[mt][nt], ah[mt], bl[nt]);
                    mma_bf16(acc[mt][nt], al[mt], bh[nt]);
                }
        }
        __syncthreads();
    }

    const int mbase = bm + wr * 64 + (lid >> 2);
    const int nbase = bn + wc * 32 + (lid & 3) * 2;
#pragma unroll
    for (int mt = 0; mt < 4; ++mt) {
#pragma unroll
        for (int nt = 0; nt < 4; ++nt) {
            const int n0 = nbase + nt * 8;
            if (n0 < N) {
                const int m0 = mbase + mt * 16;
                float2 v0 = make_float2(acc[mt][nt][0], acc[mt][nt][1]);
                float2 v1 = make_float2(acc[mt][nt][2], acc[mt][nt][3]);
                *(float2*)(C + (size_t)m0 * N + n0)       = v0;
                *(float2*)(C + (size_t)(m0 + 8) * N + n0) = v1;
            }
        }
    }
}

// ---------------------------------------------------------------------------
// fp32 -> bf16 hi/lo split
// ---------------------------------------------------------------------------
__global__ void split_kernel(const float* __restrict__ src,
                             __nv_bfloat16* __restrict__ hi,
                             __nv_bfloat16* __restrict__ lo, int n)
{
    const int i = blockIdx.x * 256 + threadIdx.x;
    if (i >= n) return;
    const float x = src[i];
    const __nv_bfloat16 h = __float2bfloat16(x);
    hi[i] = h;
    lo[i] = __float2bfloat16(x - __bfloat162float(h));
}

// ---------------------------------------------------------------------------
// Depthwise causal conv (width 4) + bias + SiLU over the xBC slice of g_zx.
// ---------------------------------------------------------------------------
__global__ void conv_silu_kernel(const float* __restrict__ cw,
                                 const float* __restrict__ cb)
{
    const int idx = blockIdx.x * 256 + threadIdx.x;
    if (idx >= NTOK * CONVDIM) return;
    const int c  = idx % CONVDIM;
    const int bt = idx / CONVDIM;
    const int t  = bt % SEQLEN;
    float acc = cb[c];
#pragma unroll
    for (int k = 0; k < 4; k++) {
        const int tt = t - 3 + k;
        if (tt >= 0)
            acc = fmaf(cw[c * 4 + k],
                       g_zx[((size_t)bt + k - 3) * DINPROJ + DINNER + c], acc);
    }
    g_conv[idx] = acc / (1.f + __expf(-acc));   // silu
}

// ---------------------------------------------------------------------------
// dt_dis = softplus(dt + dt_bias); dA = exp(dt_dis * (-exp(A_log)))
// ---------------------------------------------------------------------------
__global__ void dt_kernel(const float* __restrict__ dt_bias,
                          const float* __restrict__ A_log)
{
    const int idx = blockIdx.x * 256 + threadIdx.x;
    if (idx >= NTOK * NHEADS) return;
    const int h  = idx % NHEADS;
    const int bt = idx / NHEADS;
    const float x  = g_zx[(size_t)bt * DINPROJ + DINNER + CONVDIM + h] + dt_bias[h];
    const float sp = (x > 20.f) ? x : log1pf(expf(x));
    const float Ah = -expf(A_log[h]);
    g_dt[idx] = sp;
    g_dA[idx] = expf(sp * Ah);
}

__global__ void zero_y_kernel()
{
    const int idx = blockIdx.x * 256 + threadIdx.x;
    if (idx < NTOK * DINNER) g_y[idx] = 0.f;
}

// ---------------------------------------------------------------------------
// Selective scan: 4-deep register prefetch + BATCHED reduction.
// grid = (4 n-slices, NHEADS, BATCH), 256 threads.
// thread (p = tid>>2, q = tid&3) owns state[p, nb..nb+8) in registers.
// The shfl+RED reduction is hoisted out of the per-step path and done once
// per 4 steps with all shuffles pipelined (one ~52cyc stall per 4 steps).
// ---------------------------------------------------------------------------
#define PF 4

__global__ __launch_bounds__(256) void scan_kernel()
{
    const int g4 = blockIdx.x, h = blockIdx.y, b = blockIdx.z;
    const int tid = threadIdx.x;
    const int p = tid >> 2, q = tid & 3;
    const int nb = g4 * 32 + q * 8;

    const float* rowbase = g_conv + (size_t)b * SEQLEN * CONVDIM;
    const float* dtp = g_dt + (size_t)b * SEQLEN * NHEADS + h;
    const float* dAp = g_dA + (size_t)b * SEQLEN * NHEADS + h;
    float* yout = g_y + (size_t)b * SEQLEN * DINNER + h * HEADDIM + p;

    const int xoff = h * HEADDIM + p;

    float s[8];
#pragma unroll
    for (int i = 0; i < 8; i++) s[i] = 0.f;

    float4 pB0[PF], pB1[PF], pC0[PF], pC1[PF];
    float  px[PF], pdt[PF], pdA[PF];
#pragma unroll
    for (int i = 0; i < PF; i++) {
        const float* r = rowbase + (size_t)i * CONVDIM;
        pB0[i] = *(const float4*)(r + DINNER + nb);
        pB1[i] = *(const float4*)(r + DINNER + nb + 4);
        pC0[i] = *(const float4*)(r + DINNER + DSTATE + nb);
        pC1[i] = *(const float4*)(r + DINNER + DSTATE + nb + 4);
        px[i]  = r[xoff];
        pdt[i] = dtp[(size_t)i * NHEADS];
        pdA[i] = dAp[(size_t)i * NHEADS];
    }

    for (int t = 0; t < SEQLEN; t += PF) {
        float accj[PF];
#pragma unroll
        for (int j = 0; j < PF; j++) {
            const float4 B0 = pB0[j], B1 = pB1[j], C0 = pC0[j], C1 = pC1[j];
            const float xv = px[j], dtv = pdt[j], dAv = pdA[j];

            const int tn = t + j + PF;
            if (tn < SEQLEN) {
                const float* r = rowbase + (size_t)tn * CONVDIM;
                pB0[j] = *(const float4*)(r + DINNER + nb);
                pB1[j] = *(const float4*)(r + DINNER + nb + 4);
                pC0[j] = *(const float4*)(r + DINNER + DSTATE + nb);
                pC1[j] = *(const float4*)(r + DINNER + DSTATE + nb + 4);
                px[j]  = r[xoff];
                pdt[j] = dtp[(size_t)tn * NHEADS];
                pdA[j] = dAp[(size_t)tn * NHEADS];
            }

            const float coef = dtv * xv;
            float acc;
            s[0] = fmaf(s[0], dAv, coef * B0.x); acc = s[0] * C0.x;
            s[1] = fmaf(s[1], dAv, coef * B0.y); acc = fmaf(s[1], C0.y, acc);
            s[2] = fmaf(s[2], dAv, coef * B0.z); acc = fmaf(s[2], C0.z, acc);
            s[3] = fmaf(s[3], dAv, coef * B0.w); acc = fmaf(s[3], C0.w, acc);
            s[4] = fmaf(s[4], dAv, coef * B1.x); acc = fmaf(s[4], C1.x, acc);
            s[5] = fmaf(s[5], dAv, coef * B1.y); acc = fmaf(s[5], C1.y, acc);
            s[6] = fmaf(s[6], dAv, coef * B1.z); acc = fmaf(s[6], C1.z, acc);
            s[7] = fmaf(s[7], dAv, coef * B1.w); acc = fmaf(s[7], C1.w, acc);
            accj[j] = acc;
        }
        // batched cross-q reduction: all shuffles pipelined
        float r1[PF];
#pragma unroll
        for (int j = 0; j < PF; j++)
            r1[j] = __shfl_xor_sync(0xffffffffu, accj[j], 1);
#pragma unroll
        for (int j = 0; j < PF; j++) accj[j] += r1[j];
#pragma unroll
        for (int j = 0; j < PF; j++)
            r1[j] = __shfl_xor_sync(0xffffffffu, accj[j], 2);
#pragma unroll
        for (int j = 0; j < PF; j++) accj[j] += r1[j];
        if (q == 0) {
#pragma unroll
            for (int j = 0; j < PF; j++)
                atomicAdd(yout + (size_t)(t + j) * DINNER, accj[j]);
        }
    }
}

// ---------------------------------------------------------------------------
// y += x*D; yz = y*silu(z); RMSNorm(yz) * norm_w  -> bf16 hi/lo (GEMM2 input)
// ---------------------------------------------------------------------------
__global__ __launch_bounds__(256) void gate_norm_kernel(
    const float* __restrict__ Dv, const float* __restrict__ nw)
{
    const int bt = blockIdx.x;
    const float* zrow = g_zx   + (size_t)bt * DINPROJ;
    const float* xrow = g_conv + (size_t)bt * CONVDIM;
    const float* yrow = g_y    + (size_t)bt * DINNER;

    float v[6];
    float ss = 0.f;
#pragma unroll
    for (int i = 0; i < 6; i++) {
        const int c = threadIdx.x + i * 256;
        const float yv = fmaf(xrow[c], Dv[c >> 6], yrow[c]);
        const float z  = zrow[c];
        const float gz = z / (1.f + __expf(-z));
        const float val = yv * gz;
        v[i] = val;
        ss = fmaf(val, val, ss);
    }
#pragma unroll
    for (int o = 16; o; o >>= 1) ss += __shfl_xor_sync(0xffffffffu, ss, o);
    __shared__ float sred[8];
    if ((threadIdx.x & 31) == 0) sred[threadIdx.x >> 5] = ss;
    __syncthreads();
    float tot = 0.f;
#pragma unroll
    for (int i = 0; i < 8; i++) tot += sred[i];
    const float scale = rsqrtf(tot * (1.f / DINNER) + 1e-5f);

    __nv_bfloat16* yh = g_yn_hi + (size_t)bt * DINNER;
    __nv_bfloat16* yl = g_yn_lo + (size_t)bt * DINNER;
#pragma unroll
    for (int i = 0; i < 6; i++) {
        const int c = threadIdx.x + i * 256;
        const float val = v[i] * scale * nw[c];
        const __nv_bfloat16 h = __float2bfloat16(val);
        yh[c] = h;
        yl[c] = __float2bfloat16(val - __bfloat162float(h));
    }
}

// ---------------------------------------------------------------------------
// Launch
// ---------------------------------------------------------------------------
extern "C" void kernel_launch(void* const* d_in, const int* in_sizes, int n_in,
                              void* d_out, int out_size)
{
    const float* u          = (const float*)d_in[0];
    const float* in_proj_w  = (const float*)d_in[1];
    const float* conv_w     = (const float*)d_in[2];
    const float* conv_b     = (const float*)d_in[3];
    const float* dt_bias    = (const float*)d_in[4];
    const float* A_log      = (const float*)d_in[5];
    const float* Dv         = (const float*)d_in[6];
    const float* norm_w     = (const float*)d_in[7];
    const float* out_proj_w = (const float*)d_in[8];
    float* out = (float*)d_out;

    float* zx = nullptr;
    __nv_bfloat16 *uh, *ul, *w1h, *w1l, *w2h, *w2l, *ynh, *ynl;
    cudaGetSymbolAddress((void**)&zx,  g_zx);
    cudaGetSymbolAddress((void**)&uh,  g_u_hi);
    cudaGetSymbolAddress((void**)&ul,  g_u_lo);
    cudaGetSymbolAddress((void**)&w1h, g_w1_hi);
    cudaGetSymbolAddress((void**)&w1l, g_w1_lo);
    cudaGetSymbolAddress((void**)&w2h, g_w2_hi);
    cudaGetSymbolAddress((void**)&w2l, g_w2_lo);
    cudaGetSymbolAddress((void**)&ynh, g_yn_hi);
    cudaGetSymbolAddress((void**)&ynl, g_yn_lo);

    cudaFuncSetAttribute(gemm_mma,
                         cudaFuncAttributeMaxDynamicSharedMemorySize, GEMM_SMEM);

    // 0) bf16 hi/lo splits for GEMM operands
    split_kernel<<<(NTOK * DMODEL + 255) / 256, 256>>>(u, uh, ul, NTOK * DMODEL);
    split_kernel<<<(DINPROJ * DMODEL + 255) / 256, 256>>>(in_proj_w, w1h, w1l,
                                                          DINPROJ * DMODEL);
    split_kernel<<<(DMODEL * DINNER + 255) / 256, 256>>>(out_proj_w, w2h, w2l,
                                                         DMODEL * DINNER);

    // 1) zxbcdt = u @ in_proj_w^T   (4096 x 3352, K=768) — HMMA bf16x3
    dim3 g1((DINPROJ + 127) / 128, NTOK / 128);
    gemm_mma<<<g1, 256, GEMM_SMEM>>>(uh, ul, w1h, w1l, zx,
                                     NTOK, DINPROJ, DMODEL);

    // 2) depthwise causal conv + silu on xBC slice
    conv_silu_kernel<<<(NTOK * CONVDIM + 255) / 256, 256>>>(conv_w, conv_b);

    // 3) dt softplus / dA
    dt_kernel<<<(NTOK * NHEADS + 255) / 256, 256>>>(dt_bias, A_log);

    // 4) zero scan accumulator
    zero_y_kernel<<<(NTOK * DINNER + 255) / 256, 256>>>();

    // 5) selective scan (prefetch + batched reduction)
    scan_kernel<<<dim3(4, NHEADS, BATCH), 256>>>();

    // 6) gate + RMSNorm -> bf16 hi/lo
    gate_norm_kernel<<<NTOK, 256>>>(Dv, norm_w);

    // 7) out = yn @ out_proj_w^T   (4096 x 768, K=1536) — HMMA bf16x3
    dim3 g2((DMODEL + 127) / 128, NTOK / 128);
    gemm_mma<<<g2, 256, GEMM_SMEM>>>(ynh, ynl, w2h, w2l, out,
                                     NTOK, DMODEL, DINNER);
}

// round 8
// speedup vs baseline: 1.6692x; 1.4735x over previous
#include <cuda_runtime.h>
#include <cuda_bf16.h>
#include <math.h>
#include <stdint.h>

#define BATCH   2
#define SEQLEN  2048
#define NTOK    (BATCH*SEQLEN)        // 4096
#define DMODEL  768
#define DINNER  1536
#define DSTATE  128
#define HEADDIM 64
#define NHEADS  24
#define CONVDIM 1792                  // DINNER + 2*DSTATE
#define DINPROJ 3352                  // 2*DINNER + 2*DSTATE + NHEADS
#define CT      64                    // chunk tokens
#define NCH     (SEQLEN/CT)           // 32 chunks per sequence

// ---------------------------------------------------------------------------
// Scratch buffers (device globals — no allocations allowed)
// ---------------------------------------------------------------------------
__device__ __align__(128) float g_zx[NTOK * DINPROJ];     // in_proj output
__device__ __align__(128) float g_conv[NTOK * CONVDIM];   // conv+silu (x | B | C)
__device__ __align__(128) float g_dt[NTOK * NHEADS];      // softplus(dt + bias)
__device__ __align__(128) float g_a[NTOK * NHEADS];       // A * dt  (log decay)
__device__ __align__(128) float g_ecum[NTOK * NHEADS];    // exp(within-chunk cumsum)
__device__ __align__(128) float g_ptot[BATCH*NHEADS*NCH]; // per-chunk total decay
__device__ __align__(128) float g_y[NTOK * DINNER];       // scan output
__device__ __align__(128) float g_cstate[BATCH*NHEADS*NCH*HEADDIM*DSTATE]; // chunk-local states
__device__ __align__(128) float g_istate[BATCH*NHEADS*NCH*HEADDIM*DSTATE]; // chunk-entry states

// bf16 hi/lo split operands for tensor-core GEMMs
__device__ __align__(128) __nv_bfloat16 g_u_hi[NTOK * DMODEL];
__device__ __align__(128) __nv_bfloat16 g_u_lo[NTOK * DMODEL];
__device__ __align__(128) __nv_bfloat16 g_w1_hi[DINPROJ * DMODEL];
__device__ __align__(128) __nv_bfloat16 g_w1_lo[DINPROJ * DMODEL];
__device__ __align__(128) __nv_bfloat16 g_w2_hi[DMODEL * DINNER];
__device__ __align__(128) __nv_bfloat16 g_w2_lo[DMODEL * DINNER];
__device__ __align__(128) __nv_bfloat16 g_yn_hi[NTOK * DINNER];
__device__ __align__(128) __nv_bfloat16 g_yn_lo[NTOK * DINNER];

// ---------------------------------------------------------------------------
// MMA helpers (baseline PTX — works under compute_103 virtual arch)
// ---------------------------------------------------------------------------
static __device__ __forceinline__ uint32_t smem_u32(const void* p) {
    return (uint32_t)__cvta_generic_to_shared(p);
}

static __device__ __forceinline__ void mma_bf16(
    float* d, const uint32_t* a, const uint32_t* b)
{
    asm volatile(
        "mma.sync.aligned.m16n8k16.row.col.f32.bf16.bf16.f32 "
        "{%0,%1,%2,%3}, {%4,%5,%6,%7}, {%8,%9}, {%0,%1,%2,%3};"
        : "+f"(d[0]), "+f"(d[1]), "+f"(d[2]), "+f"(d[3])
        : "r"(a[0]), "r"(a[1]), "r"(a[2]), "r"(a[3]), "r"(b[0]), "r"(b[1]));
}

static __device__ __forceinline__ void ldmatrix_x4(uint32_t* r, uint32_t addr)
{
    asm volatile("ldmatrix.sync.aligned.m8n8.x4.shared.b16 {%0,%1,%2,%3}, [%4];"
                 : "=r"(r[0]), "=r"(r[1]), "=r"(r[2]), "=r"(r[3]) : "r"(addr));
}

static __device__ __forceinline__ void ldmatrix_x2(uint32_t* r, uint32_t addr)
{
    asm volatile("ldmatrix.sync.aligned.m8n8.x2.shared.b16 {%0,%1}, [%2];"
                 : "=r"(r[0]), "=r"(r[1]) : "r"(addr));
}

static __device__ __forceinline__ void ldmatrix_x2_trans(uint32_t* r, uint32_t addr)
{
    asm volatile("ldmatrix.sync.aligned.m8n8.x2.trans.shared.b16 {%0,%1}, [%2];"
                 : "=r"(r[0]), "=r"(r[1]) : "r"(addr));
}

static __device__ __forceinline__ void cp16(uint32_t dst, const void* src, int sz)
{
    asm volatile("cp.async.cg.shared.global [%0], [%1], 16, %2;"
                 :: "r"(dst), "l"(src), "r"(sz));
}

// split fp32x4 into packed bf16 hi/lo (uint2 each)
static __device__ __forceinline__ void split4(float4 v, uint2& hi, uint2& lo)
{
    __nv_bfloat16 h0=__float2bfloat16(v.x), h1=__float2bfloat16(v.y),
                  h2=__float2bfloat16(v.z), h3=__float2bfloat16(v.w);
    __nv_bfloat16 l0=__float2bfloat16(v.x-__bfloat162float(h0)),
                  l1=__float2bfloat16(v.y-__bfloat162float(h1)),
                  l2=__float2bfloat16(v.z-__bfloat162float(h2)),
                  l3=__float2bfloat16(v.w-__bfloat162float(h3));
    hi.x = ((uint32_t)__bfloat16_as_ushort(h1)<<16) | __bfloat16_as_ushort(h0);
    hi.y = ((uint32_t)__bfloat16_as_ushort(h3)<<16) | __bfloat16_as_ushort(h2);
    lo.x = ((uint32_t)__bfloat16_as_ushort(l1)<<16) | __bfloat16_as_ushort(l0);
    lo.y = ((uint32_t)__bfloat16_as_ushort(l3)<<16) | __bfloat16_as_ushort(l2);
}

// ---------------------------------------------------------------------------
// bf16x3 GEMM via mma.sync:  C[M,N] = A[M,K] @ B[N,K]^T  (R4 proven form)
// ---------------------------------------------------------------------------
#define ROWB   80
#define MATB   (128 * ROWB)
#define STAGEB (4 * MATB)
#define GEMM_SMEM (2 * STAGEB)

__global__ void __launch_bounds__(256) gemm_mma(
    const __nv_bfloat16* __restrict__ Ah, const __nv_bfloat16* __restrict__ Al,
    const __nv_bfloat16* __restrict__ Bh, const __nv_bfloat16* __restrict__ Bl,
    float* __restrict__ C, int M, int N, int K)
{
    extern __shared__ __align__(128) char smem[];
    const uint32_t sb = smem_u32(smem);
    const int tid = threadIdx.x;
    const int wid = tid >> 5, lid = tid & 31;
    const int bm = blockIdx.y * 128;
    const int bn = blockIdx.x * 128;
    const int wr = wid & 1;
    const int wc = wid >> 1;

    float acc[4][4][4];
#pragma unroll
    for (int i = 0; i < 4; i++)
#pragma unroll
        for (int j = 0; j < 4; j++)
#pragma unroll
            for (int k = 0; k < 4; k++) acc[i][j][k] = 0.f;

    const int lrow = tid >> 1;
    const int lch  = (tid & 1) * 2;
    const int bok  = (bn + lrow) < N ? 16 : 0;
    const size_t arowoff = (size_t)(bm + lrow) * K;
    const size_t browoff = (size_t)(bok ? (bn + lrow) : 0) * K;
    const uint32_t dst0 = sb + lrow * ROWB + lch * 16;

    const int NC = K >> 5;

    {
        const size_t ao = arowoff + lch * 8;
        const size_t bo = browoff + lch * 8;
        cp16(dst0,             Ah + ao, 16); cp16(dst0 + 16,            Ah + ao + 8, 16);
        cp16(dst0 + MATB,      Al + ao, 16); cp16(dst0 + MATB + 16,     Al + ao + 8, 16);
        cp16(dst0 + 2*MATB,    Bh + bo, bok); cp16(dst0 + 2*MATB + 16,  Bh + bo + 8, bok);
        cp16(dst0 + 3*MATB,    Bl + bo, bok); cp16(dst0 + 3*MATB + 16,  Bl + bo + 8, bok);
        asm volatile("cp.async.commit_group;");
    }

    for (int c = 0; c < NC; ++c) {
        if (c + 1 < NC) {
            const uint32_t d = dst0 + ((c + 1) & 1) * STAGEB;
            const size_t ao = arowoff + (size_t)(c + 1) * 32 + lch * 8;
            const size_t bo = browoff + (size_t)(c + 1) * 32 + lch * 8;
            cp16(d,            Ah + ao, 16); cp16(d + 16,           Ah + ao + 8, 16);
            cp16(d + MATB,     Al + ao, 16); cp16(d + MATB + 16,    Al + ao + 8, 16);
            cp16(d + 2*MATB,   Bh + bo, bok); cp16(d + 2*MATB + 16, Bh + bo + 8, bok);
            cp16(d + 3*MATB,   Bl + bo, bok); cp16(d + 3*MATB + 16, Bl + bo + 8, bok);
            asm volatile("cp.async.commit_group;");
            asm volatile("cp.async.wait_group 1;");
        } else {
            asm volatile("cp.async.wait_group 0;");
        }
        __syncthreads();

        const uint32_t st = sb + (c & 1) * STAGEB;
#pragma unroll
        for (int ks = 0; ks < 2; ++ks) {
            uint32_t ah[4][4], al[4][4], bh[4][2], bl[4][2];
            const int arow = wr * 64 + (lid & 15);
            const int akc  = ks * 2 + (lid >> 4);
#pragma unroll
            for (int mt = 0; mt < 4; ++mt) {
                const uint32_t a = st + (arow + mt * 16) * ROWB + akc * 16;
                ldmatrix_x4(ah[mt], a);
                ldmatrix_x4(al[mt], a + MATB);
            }
            const int brow = wc * 32 + (lid & 7);
            const int bkc  = ks * 2 + ((lid >> 3) & 1);
#pragma unroll
            for (int nt = 0; nt < 4; ++nt) {
                const uint32_t b = st + 2*MATB + (brow + nt * 8) * ROWB + bkc * 16;
                ldmatrix_x2(bh[nt], b);
                ldmatrix_x2(bl[nt], b + MATB);
            }
#pragma unroll
            for (int mt = 0; mt < 4; ++mt)
#pragma unroll
                for (int nt = 0; nt < 4; ++nt) {
                    mma_bf16(acc[mt][nt], ah[mt], bh[nt]);
                    mma_bf16(acc[mt][nt], ah[mt], bl[nt]);
                    mma_bf16(acc[mt][nt], al[mt], bh[nt]);
                }
        }
        __syncthreads();
    }

    const int mbase = bm + wr * 64 + (lid >> 2);
    const int nbase = bn + wc * 32 + (lid & 3) * 2;
#pragma unroll
    for (int mt = 0; mt < 4; ++mt) {
#pragma unroll
        for (int nt = 0; nt < 4; ++nt) {
            const int n0 = nbase + nt * 8;
            if (n0 < N) {
                const int m0 = mbase + mt * 16;
                float2 v0 = make_float2(acc[mt][nt][0], acc[mt][nt][1]);
                float2 v1 = make_float2(acc[mt][nt][2], acc[mt][nt][3]);
                *(float2*)(C + (size_t)m0 * N + n0)       = v0;
                *(float2*)(C + (size_t)(m0 + 8) * N + n0) = v1;
            }
        }
    }
}

// ---------------------------------------------------------------------------
// fp32 -> bf16 hi/lo split
// ---------------------------------------------------------------------------
__global__ void split_kernel(const float* __restrict__ src,
                             __nv_bfloat16* __restrict__ hi,
                             __nv_bfloat16* __restrict__ lo, int n)
{
    const int i = blockIdx.x * 256 + threadIdx.x;
    if (i >= n) return;
    const float x = src[i];
    const __nv_bfloat16 h = __float2bfloat16(x);
    hi[i] = h;
    lo[i] = __float2bfloat16(x - __bfloat162float(h));
}

// ---------------------------------------------------------------------------
// Depthwise causal conv (width 4) + bias + SiLU over the xBC slice of g_zx.
// ---------------------------------------------------------------------------
__global__ void conv_silu_kernel(const float* __restrict__ cw,
                                 const float* __restrict__ cb)
{
    const int idx = blockIdx.x * 256 + threadIdx.x;
    if (idx >= NTOK * CONVDIM) return;
    const int c  = idx % CONVDIM;
    const int bt = idx / CONVDIM;
    const int t  = bt % SEQLEN;
    float acc = cb[c];
#pragma unroll
    for (int k = 0; k < 4; k++) {
        const int tt = t - 3 + k;
        if (tt >= 0)
            acc = fmaf(cw[c * 4 + k],
                       g_zx[((size_t)bt + k - 3) * DINPROJ + DINNER + c], acc);
    }
    g_conv[idx] = acc / (1.f + __expf(-acc));   // silu
}

// ---------------------------------------------------------------------------
// dt_dis = softplus(dt + dt_bias); a = dt_dis * A  (log decay, negative)
// ---------------------------------------------------------------------------
__global__ void dt_kernel(const float* __restrict__ dt_bias,
                          const float* __restrict__ A_log)
{
    const int idx = blockIdx.x * 256 + threadIdx.x;
    if (idx >= NTOK * NHEADS) return;
    const int h  = idx % NHEADS;
    const int bt = idx / NHEADS;
    const float x  = g_zx[(size_t)bt * DINPROJ + DINNER + CONVDIM + h] + dt_bias[h];
    const float sp = (x > 20.f) ? x : log1pf(expf(x));
    const float Ah = -expf(A_log[h]);
    g_dt[idx] = sp;
    g_a[idx]  = sp * Ah;
}

// ---------------------------------------------------------------------------
// SSD chunk kernel: per (chunk, head, batch) block, 128 threads (4 warps 2x2).
//   G = C·B^T (64x64,K=128);  P = mask(exp(cum_i - cum_j)) * G * dt_j
//   Y_intra = P·X (64x64,K=64)            -> g_y
//   L[p,n]  = sum_j w_j x_j[p] B_j[n]     -> g_cstate   (ldmatrix.trans for B^T)
// All GEMMs bf16x3.
// ---------------------------------------------------------------------------
#define PB 272                   // B/C smem row pitch bytes (128 bf16 + 8 pad)
#define PX 144                   // X/P smem row pitch bytes (64 bf16 + 8 pad)
#define SM_BH 0
#define SM_BL 17408
#define SM_CH 34816
#define SM_CL 52224
#define SM_XH 69632
#define SM_XL 78848
#define SM_PH 88064
#define SM_PL 97280
#define SM_CUM 106496
#define SM_DTA 106752
#define SM_WW  107008
#define CHUNK_SMEM 107264

__global__ void __launch_bounds__(128) chunk_kernel()
{
    extern __shared__ __align__(128) char smem[];
    const uint32_t sb = smem_u32(smem);
    const int ch = blockIdx.x, h = blockIdx.y, b = blockIdx.z;
    const int tid = threadIdx.x;
    const int wid = tid >> 5, lid = tid & 31;
    const int wr = wid & 1, wc = wid >> 1;
    const size_t tb = (size_t)b * SEQLEN + (size_t)ch * CT;

    float* s_cum = (float*)(smem + SM_CUM);
    float* s_dt  = (float*)(smem + SM_DTA);
    float* s_w   = (float*)(smem + SM_WW);

    // ---- stage B, C (hi/lo bf16, pitch PB) ----
    {
        const int row = tid >> 1, c0 = (tid & 1) * 64;
        const float* src = g_conv + (tb + row) * CONVDIM + DINNER;
#pragma unroll
        for (int c = 0; c < 64; c += 4) {
            float4 v = *(const float4*)(src + c0 + c);
            uint2 hi, lo; split4(v, hi, lo);
            *(uint2*)(smem + SM_BH + row * PB + (c0 + c) * 2) = hi;
            *(uint2*)(smem + SM_BL + row * PB + (c0 + c) * 2) = lo;
            float4 u = *(const float4*)(src + DSTATE + c0 + c);
            split4(u, hi, lo);
            *(uint2*)(smem + SM_CH + row * PB + (c0 + c) * 2) = hi;
            *(uint2*)(smem + SM_CL + row * PB + (c0 + c) * 2) = lo;
        }
    }
    // ---- stage X transposed: Xs[p][t] (hi/lo, pitch PX) ----
    {
        const int t = tid >> 1, p0 = (tid & 1) * 32;
        const float* src = g_conv + (tb + t) * CONVDIM + h * HEADDIM;
#pragma unroll
        for (int p = 0; p < 32; p += 4) {
            float4 v = *(const float4*)(src + p0 + p);
            const float vv[4] = {v.x, v.y, v.z, v.w};
#pragma unroll
            for (int i = 0; i < 4; i++) {
                const __nv_bfloat16 hb = __float2bfloat16(vv[i]);
                const __nv_bfloat16 lb = __float2bfloat16(vv[i] - __bfloat162float(hb));
                *(unsigned short*)(smem + SM_XH + (p0 + p + i) * PX + t * 2) =
                    __bfloat16_as_ushort(hb);
                *(unsigned short*)(smem + SM_XL + (p0 + p + i) * PX + t * 2) =
                    __bfloat16_as_ushort(lb);
            }
        }
    }
    // ---- warp 0: within-chunk inclusive cumsum of a (64) ----
    if (wid == 0) {
        const float a0 = g_a[(tb + 2 * lid)     * NHEADS + h];
        const float a1 = g_a[(tb + 2 * lid + 1) * NHEADS + h];
        const float ps = a0 + a1;
        float sc = ps;
#pragma unroll
        for (int off = 1; off < 32; off <<= 1) {
            const float t = __shfl_up_sync(0xffffffffu, sc, off);
            if (lid >= off) sc += t;
        }
        float excl = __shfl_up_sync(0xffffffffu, sc, 1);
        if (lid == 0) excl = 0.f;
        s_cum[2 * lid]     = excl + a0;
        s_cum[2 * lid + 1] = excl + ps;
    }
    if (tid < 64) s_dt[tid] = g_dt[(tb + tid) * NHEADS + h];
    __syncthreads();

    if (tid < 64) {
        const float ct = s_cum[tid], tot = s_cum[63];
        s_w[tid] = expf(tot - ct) * s_dt[tid];
        g_ecum[(tb + tid) * NHEADS + h] = expf(ct);
        if (tid == 63)
            g_ptot[((size_t)b * NHEADS + h) * NCH + ch] = expf(tot);
    }

    // ---- G = C·B^T (64x64, K=128), bf16x3, warp 2x2 (32x32 each) ----
    float gacc[2][4][4];
#pragma unroll
    for (int i = 0; i < 2; i++)
#pragma unroll
        for (int j = 0; j < 4; j++)
#pragma unroll
            for (int k = 0; k < 4; k++) gacc[i][j][k] = 0.f;
#pragma unroll
    for (int ks = 0; ks < 8; ++ks) {
        uint32_t ah[2][4], al[2][4], bh2[4][2], bl2[4][2];
        const int arow = wr * 32 + (lid & 15);
        const int akc  = ks * 2 + (lid >> 4);
#pragma unroll
        for (int mt = 0; mt < 2; ++mt) {
            const uint32_t a = sb + SM_CH + (arow + mt * 16) * PB + akc * 16;
            ldmatrix_x4(ah[mt], a);
            ldmatrix_x4(al[mt], a + (SM_CL - SM_CH));
        }
        const int brow = wc * 32 + (lid & 7);
        const int bkc  = ks * 2 + ((lid >> 3) & 1);
#pragma unroll
        for (int nt = 0; nt < 4; ++nt) {
            const uint32_t bp = sb + SM_BH + (brow + nt * 8) * PB + bkc * 16;
            ldmatrix_x2(bh2[nt], bp);
            ldmatrix_x2(bl2[nt], bp + (SM_BL - SM_BH));
        }
#pragma unroll
        for (int mt = 0; mt < 2; ++mt)
#pragma unroll
            for (int nt = 0; nt < 4; ++nt) {
                mma_bf16(gacc[mt][nt], ah[mt], bh2[nt]);
                mma_bf16(gacc[mt][nt], ah[mt], bl2[nt]);
                mma_bf16(gacc[mt][nt], al[mt], bh2[nt]);
            }
    }

    // ---- P = mask * G * dt  -> smem (bf16 hi/lo, [t][j], pitch PX) ----
#pragma unroll
    for (int mt = 0; mt < 2; ++mt)
#pragma unroll
        for (int nt = 0; nt < 4; ++nt)
#pragma unroll
            for (int r = 0; r < 4; ++r) {
                const int t1 = wr * 32 + mt * 16 + (lid >> 2) + ((r >> 1) ? 8 : 0);
                const int t2 = wc * 32 + nt * 8 + (lid & 3) * 2 + (r & 1);
                float pv = 0.f;
                if (t1 >= t2)
                    pv = __expf(s_cum[t1] - s_cum[t2]) * gacc[mt][nt][r] * s_dt[t2];
                const __nv_bfloat16 hb = __float2bfloat16(pv);
                const __nv_bfloat16 lb = __float2bfloat16(pv - __bfloat162float(hb));
                *(unsigned short*)(smem + SM_PH + t1 * PX + t2 * 2) =
                    __bfloat16_as_ushort(hb);
                *(unsigned short*)(smem + SM_PL + t1 * PX + t2 * 2) =
                    __bfloat16_as_ushort(lb);
            }
    __syncthreads();

    // ---- Y_intra = P·X (64x64, K=64): A=P[t][j], B-op=X[p][j] ----
    {
        float yacc[2][4][4];
#pragma unroll
        for (int i = 0; i < 2; i++)
#pragma unroll
            for (int j = 0; j < 4; j++)
#pragma unroll
                for (int k = 0; k < 4; k++) yacc[i][j][k] = 0.f;
#pragma unroll
        for (int ks = 0; ks < 4; ++ks) {
            uint32_t ah[2][4], al[2][4], bh2[4][2], bl2[4][2];
            const int arow = wr * 32 + (lid & 15);
            const int akc  = ks * 2 + (lid >> 4);
#pragma unroll
            for (int mt = 0; mt < 2; ++mt) {
                const uint32_t a = sb + SM_PH + (arow + mt * 16) * PX + akc * 16;
                ldmatrix_x4(ah[mt], a);
                ldmatrix_x4(al[mt], a + (SM_PL - SM_PH));
            }
            const int brow = wc * 32 + (lid & 7);
            const int bkc  = ks * 2 + ((lid >> 3) & 1);
#pragma unroll
            for (int nt = 0; nt < 4; ++nt) {
                const uint32_t bp = sb + SM_XH + (brow + nt * 8) * PX + bkc * 16;
                ldmatrix_x2(bh2[nt], bp);
                ldmatrix_x2(bl2[nt], bp + (SM_XL - SM_XH));
            }
#pragma unroll
            for (int mt = 0; mt < 2; ++mt)
#pragma unroll
                for (int nt = 0; nt < 4; ++nt) {
                    mma_bf16(yacc[mt][nt], ah[mt], bh2[nt]);
                    mma_bf16(yacc[mt][nt], ah[mt], bl2[nt]);
                    mma_bf16(yacc[mt][nt], al[mt], bh2[nt]);
                }
        }
        // store Y_intra
#pragma unroll
        for (int mt = 0; mt < 2; ++mt)
#pragma unroll
            for (int nt = 0; nt < 4; ++nt) {
                const int t0 = wr * 32 + mt * 16 + (lid >> 2);
                const int p0 = wc * 32 + nt * 8 + (lid & 3) * 2;
                *(float2*)(g_y + (tb + t0) * DINNER + h * HEADDIM + p0) =
                    make_float2(yacc[mt][nt][0], yacc[mt][nt][1]);
                *(float2*)(g_y + (tb + t0 + 8) * DINNER + h * HEADDIM + p0) =
                    make_float2(yacc[mt][nt][2], yacc[mt][nt][3]);
            }
    }
    __syncthreads();   // all P reads done; reuse P region for Xw

    // ---- Xw[p][j] = x[j,p] * w_j  into P region ----
    {
        const int p = tid >> 1, j0 = (tid & 1) * 32;
#pragma unroll
        for (int j = 0; j < 32; ++j) {
            const int jj = j0 + j;
            const float xv =
                __bfloat162float(__ushort_as_bfloat16(
                    *(unsigned short*)(smem + SM_XH + p * PX + jj * 2))) +
                __bfloat162float(__ushort_as_bfloat16(
                    *(unsigned short*)(smem + SM_XL + p * PX + jj * 2)));
            const float xw = xv * s_w[jj];
            const __nv_bfloat16 hb = __float2bfloat16(xw);
            const __nv_bfloat16 lb = __float2bfloat16(xw - __bfloat162float(hb));
            *(unsigned short*)(smem + SM_PH + p * PX + jj * 2) =
                __bfloat16_as_ushort(hb);
            *(unsigned short*)(smem + SM_PL + p * PX + jj * 2) =
                __bfloat16_as_ushort(lb);
        }
    }
    __syncthreads();

    // ---- L = Xw·B (64p x 128n, K=64): B-op = B^T via ldmatrix.trans ----
    {
        float lacc[2][8][4];
#pragma unroll
        for (int i = 0; i < 2; i++)
#pragma unroll
            for (int j = 0; j < 8; j++)
#pragma unroll
                for (int k = 0; k < 4; k++) lacc[i][j][k] = 0.f;
#pragma unroll
        for (int ks = 0; ks < 4; ++ks) {
            uint32_t ah[2][4], al[2][4];
            const int arow = wr * 32 + (lid & 15);
            const int akc  = ks * 2 + (lid >> 4);
#pragma unroll
            for (int mt = 0; mt < 2; ++mt) {
                const uint32_t a = sb + SM_PH + (arow + mt * 16) * PX + akc * 16;
                ldmatrix_x4(ah[mt], a);
                ldmatrix_x4(al[mt], a + (SM_PL - SM_PH));
            }
            const int j0 = ks * 16 + (lid & 15);
#pragma unroll
            for (int nt = 0; nt < 8; ++nt) {
                const int n0 = wc * 64 + nt * 8;
                uint32_t bh2[2], bl2[2];
                const uint32_t bp = sb + SM_BH + j0 * PB + n0 * 2;
                ldmatrix_x2_trans(bh2, bp);
                ldmatrix_x2_trans(bl2, bp + (SM_BL - SM_BH));
#pragma unroll
                for (int mt = 0; mt < 2; ++mt) {
                    mma_bf16(lacc[mt][nt], ah[mt], bh2);
                    mma_bf16(lacc[mt][nt], ah[mt], bl2);
                    mma_bf16(lacc[mt][nt], al[mt], bh2);
                }
            }
        }
        float* Lout = g_cstate +
            (((size_t)b * NHEADS + h) * NCH + ch) * (HEADDIM * DSTATE);
#pragma unroll
        for (int mt = 0; mt < 2; ++mt)
#pragma unroll
            for (int nt = 0; nt < 8; ++nt) {
                const int p0 = wr * 32 + mt * 16 + (lid >> 2);
                const int n0 = wc * 64 + nt * 8 + (lid & 3) * 2;
                *(float2*)(Lout + (size_t)p0 * DSTATE + n0) =
                    make_float2(lacc[mt][nt][0], lacc[mt][nt][1]);
                *(float2*)(Lout + (size_t)(p0 + 8) * DSTATE + n0) =
                    make_float2(lacc[mt][nt][2], lacc[mt][nt][3]);
            }
    }
}

// ---------------------------------------------------------------------------
// Sequential combine over chunks: istate[c] = S_c;  S_{c+1} = ptot_c*S_c + L_c
// grid (NHEADS, BATCH), 256 threads x 32 floats.
// ---------------------------------------------------------------------------
__global__ __launch_bounds__(256) void combine_kernel()
{
    const int h = blockIdx.x, b = blockIdx.y;
    const int tid = threadIdx.x;
    const size_t off = (size_t)tid * 32;
    float4 acc[8];
#pragma unroll
    for (int r = 0; r < 8; r++) acc[r] = make_float4(0.f, 0.f, 0.f, 0.f);

    for (int c = 0; c < NCH; ++c) {
        const size_t base = (((size_t)b * NHEADS + h) * NCH + c) * (HEADDIM * DSTATE);
#pragma unroll
        for (int r = 0; r < 8; r++)
            *(float4*)(g_istate + base + off + r * 4) = acc[r];
        const float P = g_ptot[((size_t)b * NHEADS + h) * NCH + c];
#pragma unroll
        for (int r = 0; r < 8; r++) {
            const float4 f = *(const float4*)(g_cstate + base + off + r * 4);
            acc[r].x = fmaf(acc[r].x, P, f.x);
            acc[r].y = fmaf(acc[r].y, P, f.y);
            acc[r].z = fmaf(acc[r].z, P, f.z);
            acc[r].w = fmaf(acc[r].w, P, f.w);
        }
    }
}

// ---------------------------------------------------------------------------
// Inter-chunk: Y[t,p] += ecum_t * (C_t · S0[p,:])  — 64x64 GEMM, K=128.
// grid (NCH-1, NHEADS, BATCH), 128 threads (4 warps 2x2), bf16x3.
// ---------------------------------------------------------------------------
#define ISM_CH 0
#define ISM_CL 17408
#define ISM_SH 34816
#define ISM_SL 52224
#define ISM_EC 69632
#define INTER_SMEM 69888

__global__ void __launch_bounds__(128) inter_kernel()
{
    extern __shared__ __align__(128) char smem[];
    const uint32_t sb = smem_u32(smem);
    const int ch = blockIdx.x + 1, h = blockIdx.y, b = blockIdx.z;
    const int tid = threadIdx.x;
    const int wid = tid >> 5, lid = tid & 31;
    const int wr = wid & 1, wc = wid >> 1;
    const size_t tb = (size_t)b * SEQLEN + (size_t)ch * CT;

    // stage C (t x n) and S0 (p x n), both pitch PB
    {
        const int row = tid >> 1, c0 = (tid & 1) * 64;
        const float* csrc = g_conv + (tb + row) * CONVDIM + DINNER + DSTATE;
        const float* ssrc = g_istate +
            (((size_t)b * NHEADS + h) * NCH + ch) * (HEADDIM * DSTATE) +
            (size_t)row * DSTATE;
#pragma unroll
        for (int c = 0; c < 64; c += 4) {
            float4 v = *(const float4*)(csrc + c0 + c);
            uint2 hi, lo; split4(v, hi, lo);
            *(uint2*)(smem + ISM_CH + row * PB + (c0 + c) * 2) = hi;
            *(uint2*)(smem + ISM_CL + row * PB + (c0 + c) * 2) = lo;
            float4 u = *(const float4*)(ssrc + c0 + c);
            split4(u, hi, lo);
            *(uint2*)(smem + ISM_SH + row * PB + (c0 + c) * 2) = hi;
            *(uint2*)(smem + ISM_SL + row * PB + (c0 + c) * 2) = lo;
        }
    }
    if (tid < 64)
        ((float*)(smem + ISM_EC))[tid] = g_ecum[(tb + tid) * NHEADS + h];
    __syncthreads();

    float acc[2][4][4];
#pragma unroll
    for (int i = 0; i < 2; i++)
#pragma unroll
        for (int j = 0; j < 4; j++)
#pragma unroll
            for (int k = 0; k < 4; k++) acc[i][j][k] = 0.f;

#pragma unroll
    for (int ks = 0; ks < 8; ++ks) {
        uint32_t ah[2][4], al[2][4], bh2[4][2], bl2[4][2];
        const int arow = wr * 32 + (lid & 15);
        const int akc  = ks * 2 + (lid >> 4);
#pragma unroll
        for (int mt = 0; mt < 2; ++mt) {
            const uint32_t a = sb + ISM_CH + (arow + mt * 16) * PB + akc * 16;
            ldmatrix_x4(ah[mt], a);
            ldmatrix_x4(al[mt], a + (ISM_CL - ISM_CH));
        }
        const int brow = wc * 32 + (lid & 7);
        const int bkc  = ks * 2 + ((lid >> 3) & 1);
#pragma unroll
        for (int nt = 0; nt < 4; ++nt) {
            const uint32_t bp = sb + ISM_SH + (brow + nt * 8) * PB + bkc * 16;
            ldmatrix_x2(bh2[nt], bp);
            ldmatrix_x2(bl2[nt], bp + (ISM_SL - ISM_SH));
        }
#pragma unroll
        for (int mt = 0; mt < 2; ++mt)
#pragma unroll
            for (int nt = 0; nt < 4; ++nt) {
                mma_bf16(acc[mt][nt], ah[mt], bh2[nt]);
                mma_bf16(acc[mt][nt], ah[mt], bl2[nt]);
                mma_bf16(acc[mt][nt], al[mt], bh2[nt]);
            }
    }

    const float* s_ec = (const float*)(smem + ISM_EC);
#pragma unroll
    for (int mt = 0; mt < 2; ++mt)
#pragma unroll
        for (int nt = 0; nt < 4; ++nt) {
            const int t0 = wr * 32 + mt * 16 + (lid >> 2);
            const int p0 = wc * 32 + nt * 8 + (lid & 3) * 2;
            {
                float* yp = g_y + (tb + t0) * DINNER + h * HEADDIM + p0;
                float2 o = *(float2*)yp;
                o.x += s_ec[t0] * acc[mt][nt][0];
                o.y += s_ec[t0] * acc[mt][nt][1];
                *(float2*)yp = o;
            }
            {
                float* yp = g_y + (tb + t0 + 8) * DINNER + h * HEADDIM + p0;
                float2 o = *(float2*)yp;
                o.x += s_ec[t0 + 8] * acc[mt][nt][2];
                o.y += s_ec[t0 + 8] * acc[mt][nt][3];
                *(float2*)yp = o;
            }
        }
}

// ---------------------------------------------------------------------------
// y += x*D; yz = y*silu(z); RMSNorm(yz) * norm_w  -> bf16 hi/lo (GEMM2 input)
// ---------------------------------------------------------------------------
__global__ __launch_bounds__(256) void gate_norm_kernel(
    const float* __restrict__ Dv, const float* __restrict__ nw)
{
    const int bt = blockIdx.x;
    const float* zrow = g_zx   + (size_t)bt * DINPROJ;
    const float* xrow = g_conv + (size_t)bt * CONVDIM;
    const float* yrow = g_y    + (size_t)bt * DINNER;

    float v[6];
    float ss = 0.f;
#pragma unroll
    for (int i = 0; i < 6; i++) {
        const int c = threadIdx.x + i * 256;
        const float yv = fmaf(xrow[c], Dv[c >> 6], yrow[c]);
        const float z  = zrow[c];
        const float gz = z / (1.f + __expf(-z));
        const float val = yv * gz;
        v[i] = val;
        ss = fmaf(val, val, ss);
    }
#pragma unroll
    for (int o = 16; o; o >>= 1) ss += __shfl_xor_sync(0xffffffffu, ss, o);
    __shared__ float sred[8];
    if ((threadIdx.x & 31) == 0) sred[threadIdx.x >> 5] = ss;
    __syncthreads();
    float tot = 0.f;
#pragma unroll
    for (int i = 0; i < 8; i++) tot += sred[i];
    const float scale = rsqrtf(tot * (1.f / DINNER) + 1e-5f);

    __nv_bfloat16* yh = g_yn_hi + (size_t)bt * DINNER;
    __nv_bfloat16* yl = g_yn_lo + (size_t)bt * DINNER;
#pragma unroll
    for (int i = 0; i < 6; i++) {
        const int c = threadIdx.x + i * 256;
        const float val = v[i] * scale * nw[c];
        const __nv_bfloat16 hb = __float2bfloat16(val);
        yh[c] = hb;
        yl[c] = __float2bfloat16(val - __bfloat162float(hb));
    }
}

// ---------------------------------------------------------------------------
// Launch
// ---------------------------------------------------------------------------
extern "C" void kernel_launch(void* const* d_in, const int* in_sizes, int n_in,
                              void* d_out, int out_size)
{
    const float* u          = (const float*)d_in[0];
    const float* in_proj_w  = (const float*)d_in[1];
    const float* conv_w     = (const float*)d_in[2];
    const float* conv_b     = (const float*)d_in[3];
    const float* dt_bias    = (const float*)d_in[4];
    const float* A_log      = (const float*)d_in[5];
    const float* Dv         = (const float*)d_in[6];
    const float* norm_w     = (const float*)d_in[7];
    const float* out_proj_w = (const float*)d_in[8];
    float* out = (float*)d_out;

    float* zx = nullptr;
    __nv_bfloat16 *uh, *ul, *w1h, *w1l, *w2h, *w2l, *ynh, *ynl;
    cudaGetSymbolAddress((void**)&zx,  g_zx);
    cudaGetSymbolAddress((void**)&uh,  g_u_hi);
    cudaGetSymbolAddress((void**)&ul,  g_u_lo);
    cudaGetSymbolAddress((void**)&w1h, g_w1_hi);
    cudaGetSymbolAddress((void**)&w1l, g_w1_lo);
    cudaGetSymbolAddress((void**)&w2h, g_w2_hi);
    cudaGetSymbolAddress((void**)&w2l, g_w2_lo);
    cudaGetSymbolAddress((void**)&ynh, g_yn_hi);
    cudaGetSymbolAddress((void**)&ynl, g_yn_lo);

    cudaFuncSetAttribute(gemm_mma,
                         cudaFuncAttributeMaxDynamicSharedMemorySize, GEMM_SMEM);
    cudaFuncSetAttribute(chunk_kernel,
                         cudaFuncAttributeMaxDynamicSharedMemorySize, CHUNK_SMEM);
    cudaFuncSetAttribute(inter_kernel,
                         cudaFuncAttributeMaxDynamicSharedMemorySize, INTER_SMEM);

    // 0) bf16 hi/lo splits for GEMM operands
    split_kernel<<<(NTOK * DMODEL + 255) / 256, 256>>>(u, uh, ul, NTOK * DMODEL);
    split_kernel<<<(DINPROJ * DMODEL + 255) / 256, 256>>>(in_proj_w, w1h, w1l,
                                                          DINPROJ * DMODEL);
    split_kernel<<<(DMODEL * DINNER + 255) / 256, 256>>>(out_proj_w, w2h, w2l,
                                                         DMODEL * DINNER);

    // 1) zxbcdt = u @ in_proj_w^T   — HMMA bf16x3
    dim3 g1((DINPROJ + 127) / 128, NTOK / 128);
    gemm_mma<<<g1, 256, GEMM_SMEM>>>(uh, ul, w1h, w1l, zx,
                                     NTOK, DINPROJ, DMODEL);

    // 2) depthwise causal conv + silu
    conv_silu_kernel<<<(NTOK * CONVDIM + 255) / 256, 256>>>(conv_w, conv_b);

    // 3) dt softplus / log-decay a
    dt_kernel<<<(NTOK * NHEADS + 255) / 256, 256>>>(dt_bias, A_log);

    // 4) SSD chunk pass (intra-chunk Y + chunk-local states) — tensor cores
    chunk_kernel<<<dim3(NCH, NHEADS, BATCH), 128, CHUNK_SMEM>>>();

    // 5) combine chunk states sequentially
    combine_kernel<<<dim3(NHEADS, BATCH), 256>>>();

    // 6) inter-chunk contribution — tensor cores
    inter_kernel<<<dim3(NCH - 1, NHEADS, BATCH), 128, INTER_SMEM>>>();

    // 7) gate + RMSNorm -> bf16 hi/lo
    gate_norm_kernel<<<NTOK, 256>>>(Dv, norm_w);

    // 8) out = yn @ out_proj_w^T — HMMA bf16x3
    dim3 g2((DMODEL + 127) / 128, NTOK / 128);
    gemm_mma<<<g2, 256, GEMM_SMEM>>>(ynh, ynl, w2h, w2l, out,
                                     NTOK, DMODEL, DINNER);
}

// round 9
// speedup vs baseline: 1.7106x; 1.0248x over previous
#include <cuda_runtime.h>
#include <cuda_bf16.h>
#include <math.h>
#include <stdint.h>

#define BATCH   2
#define SEQLEN  2048
#define NTOK    (BATCH*SEQLEN)        // 4096
#define DMODEL  768
#define DINNER  1536
#define DSTATE  128
#define HEADDIM 64
#define NHEADS  24
#define CONVDIM 1792                  // DINNER + 2*DSTATE
#define DINPROJ 3352                  // 2*DINNER + 2*DSTATE + NHEADS
#define CT      64                    // chunk tokens
#define NCH     (SEQLEN/CT)           // 32 chunks per sequence

// ---------------------------------------------------------------------------
// Scratch buffers (device globals — no allocations allowed)
// ---------------------------------------------------------------------------
__device__ __align__(128) float g_zx[NTOK * DINPROJ];     // in_proj output
__device__ __align__(128) float g_conv[NTOK * CONVDIM];   // conv+silu (x | B | C)
__device__ __align__(128) float g_dt[NTOK * NHEADS];      // softplus(dt + bias)
__device__ __align__(128) float g_a[NTOK * NHEADS];       // A * dt  (log decay)
__device__ __align__(128) float g_ecum[NTOK * NHEADS];    // exp(within-chunk cumsum)
__device__ __align__(128) float g_ptot[BATCH*NHEADS*NCH]; // per-chunk total decay
__device__ __align__(128) float g_y[NTOK * DINNER];       // scan output
__device__ __align__(128) float g_cstate[BATCH*NHEADS*NCH*HEADDIM*DSTATE]; // chunk-local states
__device__ __align__(128) float g_istate[BATCH*NHEADS*NCH*HEADDIM*DSTATE]; // chunk-entry states

// bf16 hi/lo split operands for tensor-core GEMMs
__device__ __align__(128) __nv_bfloat16 g_u_hi[NTOK * DMODEL];
__device__ __align__(128) __nv_bfloat16 g_u_lo[NTOK * DMODEL];
__device__ __align__(128) __nv_bfloat16 g_w1_hi[DINPROJ * DMODEL];
__device__ __align__(128) __nv_bfloat16 g_w1_lo[DINPROJ * DMODEL];
__device__ __align__(128) __nv_bfloat16 g_w2_hi[DMODEL * DINNER];
__device__ __align__(128) __nv_bfloat16 g_w2_lo[DMODEL * DINNER];
__device__ __align__(128) __nv_bfloat16 g_yn_hi[NTOK * DINNER];
__device__ __align__(128) __nv_bfloat16 g_yn_lo[NTOK * DINNER];

// ---------------------------------------------------------------------------
// MMA helpers (baseline PTX — works under compute_103 virtual arch)
// ---------------------------------------------------------------------------
static __device__ __forceinline__ uint32_t smem_u32(const void* p) {
    return (uint32_t)__cvta_generic_to_shared(p);
}

static __device__ __forceinline__ void mma_bf16(
    float* d, const uint32_t* a, const uint32_t* b)
{
    asm volatile(
        "mma.sync.aligned.m16n8k16.row.col.f32.bf16.bf16.f32 "
        "{%0,%1,%2,%3}, {%4,%5,%6,%7}, {%8,%9}, {%0,%1,%2,%3};"
        : "+f"(d[0]), "+f"(d[1]), "+f"(d[2]), "+f"(d[3])
        : "r"(a[0]), "r"(a[1]), "r"(a[2]), "r"(a[3]), "r"(b[0]), "r"(b[1]));
}

static __device__ __forceinline__ void ldmatrix_x4(uint32_t* r, uint32_t addr)
{
    asm volatile("ldmatrix.sync.aligned.m8n8.x4.shared.b16 {%0,%1,%2,%3}, [%4];"
                 : "=r"(r[0]), "=r"(r[1]), "=r"(r[2]), "=r"(r[3]) : "r"(addr));
}

static __device__ __forceinline__ void ldmatrix_x2(uint32_t* r, uint32_t addr)
{
    asm volatile("ldmatrix.sync.aligned.m8n8.x2.shared.b16 {%0,%1}, [%2];"
                 : "=r"(r[0]), "=r"(r[1]) : "r"(addr));
}

static __device__ __forceinline__ void ldmatrix_x2_trans(uint32_t* r, uint32_t addr)
{
    asm volatile("ldmatrix.sync.aligned.m8n8.x2.trans.shared.b16 {%0,%1}, [%2];"
                 : "=r"(r[0]), "=r"(r[1]) : "r"(addr));
}

static __device__ __forceinline__ void cp16(uint32_t dst, const void* src, int sz)
{
    asm volatile("cp.async.cg.shared.global [%0], [%1], 16, %2;"
                 :: "r"(dst), "l"(src), "r"(sz));
}

// split fp32x4 into packed bf16 hi/lo (uint2 each)
static __device__ __forceinline__ void split4(float4 v, uint2& hi, uint2& lo)
{
    __nv_bfloat16 h0=__float2bfloat16(v.x), h1=__float2bfloat16(v.y),
                  h2=__float2bfloat16(v.z), h3=__float2bfloat16(v.w);
    __nv_bfloat16 l0=__float2bfloat16(v.x-__bfloat162float(h0)),
                  l1=__float2bfloat16(v.y-__bfloat162float(h1)),
                  l2=__float2bfloat16(v.z-__bfloat162float(h2)),
                  l3=__float2bfloat16(v.w-__bfloat162float(h3));
    hi.x = ((uint32_t)__bfloat16_as_ushort(h1)<<16) | __bfloat16_as_ushort(h0);
    hi.y = ((uint32_t)__bfloat16_as_ushort(h3)<<16) | __bfloat16_as_ushort(h2);
    lo.x = ((uint32_t)__bfloat16_as_ushort(l1)<<16) | __bfloat16_as_ushort(l0);
    lo.y = ((uint32_t)__bfloat16_as_ushort(l3)<<16) | __bfloat16_as_ushort(l2);
}

// ---------------------------------------------------------------------------
// bf16x3 GEMM via mma.sync:  C[M,N] = A[M,K] @ B[N,K]^T  (R4 proven form)
// ---------------------------------------------------------------------------
#define ROWB   80
#define MATB   (128 * ROWB)
#define STAGEB (4 * MATB)
#define GEMM_SMEM (2 * STAGEB)

__global__ void __launch_bounds__(256) gemm_mma(
    const __nv_bfloat16* __restrict__ Ah, const __nv_bfloat16* __restrict__ Al,
    const __nv_bfloat16* __restrict__ Bh, const __nv_bfloat16* __restrict__ Bl,
    float* __restrict__ C, int M, int N, int K)
{
    extern __shared__ __align__(128) char smem[];
    const uint32_t sb = smem_u32(smem);
    const int tid = threadIdx.x;
    const int wid = tid >> 5, lid = tid & 31;
    const int bm = blockIdx.y * 128;
    const int bn = blockIdx.x * 128;
    const int wr = wid & 1;
    const int wc = wid >> 1;

    float acc[4][4][4];
#pragma unroll
    for (int i = 0; i < 4; i++)
#pragma unroll
        for (int j = 0; j < 4; j++)
#pragma unroll
            for (int k = 0; k < 4; k++) acc[i][j][k] = 0.f;

    const int lrow = tid >> 1;
    const int lch  = (tid & 1) * 2;
    const int bok  = (bn + lrow) < N ? 16 : 0;
    const size_t arowoff = (size_t)(bm + lrow) * K;
    const size_t browoff = (size_t)(bok ? (bn + lrow) : 0) * K;
    const uint32_t dst0 = sb + lrow * ROWB + lch * 16;

    const int NC = K >> 5;

    {
        const size_t ao = arowoff + lch * 8;
        const size_t bo = browoff + lch * 8;
        cp16(dst0,             Ah + ao, 16); cp16(dst0 + 16,            Ah + ao + 8, 16);
        cp16(dst0 + MATB,      Al + ao, 16); cp16(dst0 + MATB + 16,     Al + ao + 8, 16);
        cp16(dst0 + 2*MATB,    Bh + bo, bok); cp16(dst0 + 2*MATB + 16,  Bh + bo + 8, bok);
        cp16(dst0 + 3*MATB,    Bl + bo, bok); cp16(dst0 + 3*MATB + 16,  Bl + bo + 8, bok);
        asm volatile("cp.async.commit_group;");
    }

    for (int c = 0; c < NC; ++c) {
        if (c + 1 < NC) {
            const uint32_t d = dst0 + ((c + 1) & 1) * STAGEB;
            const size_t ao = arowoff + (size_t)(c + 1) * 32 + lch * 8;
            const size_t bo = browoff + (size_t)(c + 1) * 32 + lch * 8;
            cp16(d,            Ah + ao, 16); cp16(d + 16,           Ah + ao + 8, 16);
            cp16(d + MATB,     Al + ao, 16); cp16(d + MATB + 16,    Al + ao + 8, 16);
            cp16(d + 2*MATB,   Bh + bo, bok); cp16(d + 2*MATB + 16, Bh + bo + 8, bok);
            cp16(d + 3*MATB,   Bl + bo, bok); cp16(d + 3*MATB + 16, Bl + bo + 8, bok);
            asm volatile("cp.async.commit_group;");
            asm volatile("cp.async.wait_group 1;");
        } else {
            asm volatile("cp.async.wait_group 0;");
        }
        __syncthreads();

        const uint32_t st = sb + (c & 1) * STAGEB;
#pragma unroll
        for (int ks = 0; ks < 2; ++ks) {
            uint32_t ah[4][4], al[4][4], bh[4][2], bl[4][2];
            const int arow = wr * 64 + (lid & 15);
            const int akc  = ks * 2 + (lid >> 4);
#pragma unroll
            for (int mt = 0; mt < 4; ++mt) {
                const uint32_t a = st + (arow + mt * 16) * ROWB + akc * 16;
                ldmatrix_x4(ah[mt], a);
                ldmatrix_x4(al[mt], a + MATB);
            }
            const int brow = wc * 32 + (lid & 7);
            const int bkc  = ks * 2 + ((lid >> 3) & 1);
#pragma unroll
            for (int nt = 0; nt < 4; ++nt) {
                const uint32_t b = st + 2*MATB + (brow + nt * 8) * ROWB + bkc * 16;
                ldmatrix_x2(bh[nt], b);
                ldmatrix_x2(bl[nt], b + MATB);
            }
#pragma unroll
            for (int mt = 0; mt < 4; ++mt)
#pragma unroll
                for (int nt = 0; nt < 4; ++nt) {
                    mma_bf16(acc[mt][nt], ah[mt], bh[nt]);
                    mma_bf16(acc[mt][nt], ah[mt], bl[nt]);
                    mma_bf16(acc[mt][nt], al[mt], bh[nt]);
                }
        }
        __syncthreads();
    }

    const int mbase = bm + wr * 64 + (lid >> 2);
    const int nbase = bn + wc * 32 + (lid & 3) * 2;
#pragma unroll
    for (int mt = 0; mt < 4; ++mt) {
#pragma unroll
        for (int nt = 0; nt < 4; ++nt) {
            const int n0 = nbase + nt * 8;
            if (n0 < N) {
                const int m0 = mbase + mt * 16;
                float2 v0 = make_float2(acc[mt][nt][0], acc[mt][nt][1]);
                float2 v1 = make_float2(acc[mt][nt][2], acc[mt][nt][3]);
                *(float2*)(C + (size_t)m0 * N + n0)       = v0;
                *(float2*)(C + (size_t)(m0 + 8) * N + n0) = v1;
            }
        }
    }
}

// ---------------------------------------------------------------------------
// fp32 -> bf16 hi/lo split
// ---------------------------------------------------------------------------
__global__ void split_kernel(const float* __restrict__ src,
                             __nv_bfloat16* __restrict__ hi,
                             __nv_bfloat16* __restrict__ lo, int n)
{
    const int i = blockIdx.x * 256 + threadIdx.x;
    if (i >= n) return;
    const float x = src[i];
    const __nv_bfloat16 h = __float2bfloat16(x);
    hi[i] = h;
    lo[i] = __float2bfloat16(x - __bfloat162float(h));
}

// ---------------------------------------------------------------------------
// Depthwise causal conv (width 4) + bias + SiLU over the xBC slice of g_zx.
// ---------------------------------------------------------------------------
__global__ void conv_silu_kernel(const float* __restrict__ cw,
                                 const float* __restrict__ cb)
{
    const int idx = blockIdx.x * 256 + threadIdx.x;
    if (idx >= NTOK * CONVDIM) return;
    const int c  = idx % CONVDIM;
    const int bt = idx / CONVDIM;
    const int t  = bt % SEQLEN;
    float acc = cb[c];
#pragma unroll
    for (int k = 0; k < 4; k++) {
        const int tt = t - 3 + k;
        if (tt >= 0)
            acc = fmaf(cw[c * 4 + k],
                       g_zx[((size_t)bt + k - 3) * DINPROJ + DINNER + c], acc);
    }
    g_conv[idx] = acc / (1.f + __expf(-acc));   // silu
}

// ---------------------------------------------------------------------------
// dt_dis = softplus(dt + dt_bias); a = dt_dis * A  (log decay, negative)
// ---------------------------------------------------------------------------
__global__ void dt_kernel(const float* __restrict__ dt_bias,
                          const float* __restrict__ A_log)
{
    const int idx = blockIdx.x * 256 + threadIdx.x;
    if (idx >= NTOK * NHEADS) return;
    const int h  = idx % NHEADS;
    const int bt = idx / NHEADS;
    const float x  = g_zx[(size_t)bt * DINPROJ + DINNER + CONVDIM + h] + dt_bias[h];
    const float sp = (x > 20.f) ? x : log1pf(expf(x));
    const float Ah = -expf(A_log[h]);
    g_dt[idx] = sp;
    g_a[idx]  = sp * Ah;
}

// ---------------------------------------------------------------------------
// SSD chunk kernel: per (chunk, head, batch) block, 256 threads (8 warps 2x4).
//   G = C·B^T (64x64,K=128);  P = mask(exp(cum_i - cum_j)) * G * dt_j
//   Y_intra = P·X (64x64,K=64)            -> g_y
//   L[p,n]  = sum_j w_j x_j[p] B_j[n]     -> g_cstate   (ldmatrix.trans for B^T)
// All GEMMs bf16x3. Warp grid: wr = wid&1 (32-row half), wc = wid>>1 (4 col grps)
// ---------------------------------------------------------------------------
#define PB 272                   // B/C smem row pitch bytes (128 bf16 + 8 pad)
#define PX 144                   // X/P smem row pitch bytes (64 bf16 + 8 pad)
#define SM_BH 0
#define SM_BL 17408
#define SM_CH 34816
#define SM_CL 52224
#define SM_XH 69632
#define SM_XL 78848
#define SM_PH 88064
#define SM_PL 97280
#define SM_CUM 106496
#define SM_DTA 106752
#define SM_WW  107008
#define CHUNK_SMEM 107264

__global__ void __launch_bounds__(256) chunk_kernel()
{
    extern __shared__ __align__(128) char smem[];
    const uint32_t sb = smem_u32(smem);
    const int ch = blockIdx.x, h = blockIdx.y, b = blockIdx.z;
    const int tid = threadIdx.x;
    const int wid = tid >> 5, lid = tid & 31;
    const int wr = wid & 1, wc = wid >> 1;
    const size_t tb = (size_t)b * SEQLEN + (size_t)ch * CT;

    float* s_cum = (float*)(smem + SM_CUM);
    float* s_dt  = (float*)(smem + SM_DTA);
    float* s_w   = (float*)(smem + SM_WW);

    // ---- stage B, C (hi/lo bf16, pitch PB): 256 threads ----
    {
        const int row = tid >> 2, c0 = (tid & 3) * 32;
        const float* src = g_conv + (tb + row) * CONVDIM + DINNER;
#pragma unroll
        for (int c = 0; c < 32; c += 4) {
            float4 v = *(const float4*)(src + c0 + c);
            uint2 hi, lo; split4(v, hi, lo);
            *(uint2*)(smem + SM_BH + row * PB + (c0 + c) * 2) = hi;
            *(uint2*)(smem + SM_BL + row * PB + (c0 + c) * 2) = lo;
            float4 u = *(const float4*)(src + DSTATE + c0 + c);
            split4(u, hi, lo);
            *(uint2*)(smem + SM_CH + row * PB + (c0 + c) * 2) = hi;
            *(uint2*)(smem + SM_CL + row * PB + (c0 + c) * 2) = lo;
        }
    }
    // ---- stage X transposed: Xs[p][t] (hi/lo, pitch PX) ----
    {
        const int t = tid >> 2, p0 = (tid & 3) * 16;
        const float* src = g_conv + (tb + t) * CONVDIM + h * HEADDIM;
#pragma unroll
        for (int p = 0; p < 16; p += 4) {
            float4 v = *(const float4*)(src + p0 + p);
            const float vv[4] = {v.x, v.y, v.z, v.w};
#pragma unroll
            for (int i = 0; i < 4; i++) {
                const __nv_bfloat16 hb = __float2bfloat16(vv[i]);
                const __nv_bfloat16 lb = __float2bfloat16(vv[i] - __bfloat162float(hb));
                *(unsigned short*)(smem + SM_XH + (p0 + p + i) * PX + t * 2) =
                    __bfloat16_as_ushort(hb);
                *(unsigned short*)(smem + SM_XL + (p0 + p + i) * PX + t * 2) =
                    __bfloat16_as_ushort(lb);
            }
        }
    }
    // ---- warp 0: within-chunk inclusive cumsum of a (64) ----
    if (wid == 0) {
        const float a0 = g_a[(tb + 2 * lid)     * NHEADS + h];
        const float a1 = g_a[(tb + 2 * lid + 1) * NHEADS + h];
        const float ps = a0 + a1;
        float sc = ps;
#pragma unroll
        for (int off = 1; off < 32; off <<= 1) {
            const float t = __shfl_up_sync(0xffffffffu, sc, off);
            if (lid >= off) sc += t;
        }
        float excl = __shfl_up_sync(0xffffffffu, sc, 1);
        if (lid == 0) excl = 0.f;
        s_cum[2 * lid]     = excl + a0;
        s_cum[2 * lid + 1] = excl + ps;
    }
    if (tid >= 64 && tid < 128) s_dt[tid - 64] = g_dt[(tb + tid - 64) * NHEADS + h];
    __syncthreads();

    if (tid < 64) {
        const float ct = s_cum[tid], tot = s_cum[63];
        s_w[tid] = expf(tot - ct) * s_dt[tid];
        g_ecum[(tb + tid) * NHEADS + h] = expf(ct);
        if (tid == 63)
            g_ptot[((size_t)b * NHEADS + h) * NCH + ch] = expf(tot);
    }

    // ---- G = C·B^T (64x64, K=128), bf16x3, warp tile 32x16 (mt2 x nt2) ----
    float gacc[2][2][4];
#pragma unroll
    for (int i = 0; i < 2; i++)
#pragma unroll
        for (int j = 0; j < 2; j++)
#pragma unroll
            for (int k = 0; k < 4; k++) gacc[i][j][k] = 0.f;
#pragma unroll
    for (int ks = 0; ks < 8; ++ks) {
        uint32_t ah[2][4], al[2][4], bh2[2][2], bl2[2][2];
        const int arow = wr * 32 + (lid & 15);
        const int akc  = ks * 2 + (lid >> 4);
#pragma unroll
        for (int mt = 0; mt < 2; ++mt) {
            const uint32_t a = sb + SM_CH + (arow + mt * 16) * PB + akc * 16;
            ldmatrix_x4(ah[mt], a);
            ldmatrix_x4(al[mt], a + (SM_CL - SM_CH));
        }
        const int brow = wc * 16 + (lid & 7);
        const int bkc  = ks * 2 + ((lid >> 3) & 1);
#pragma unroll
        for (int nt = 0; nt < 2; ++nt) {
            const uint32_t bp = sb + SM_BH + (brow + nt * 8) * PB + bkc * 16;
            ldmatrix_x2(bh2[nt], bp);
            ldmatrix_x2(bl2[nt], bp + (SM_BL - SM_BH));
        }
#pragma unroll
        for (int mt = 0; mt < 2; ++mt)
#pragma unroll
            for (int nt = 0; nt < 2; ++nt) {
                mma_bf16(gacc[mt][nt], ah[mt], bh2[nt]);
                mma_bf16(gacc[mt][nt], ah[mt], bl2[nt]);
                mma_bf16(gacc[mt][nt], al[mt], bh2[nt]);
            }
    }

    // ---- P = mask * G * dt  -> smem (bf16 hi/lo, [t][j], pitch PX) ----
#pragma unroll
    for (int mt = 0; mt < 2; ++mt)
#pragma unroll
        for (int nt = 0; nt < 2; ++nt)
#pragma unroll
            for (int r = 0; r < 4; ++r) {
                const int t1 = wr * 32 + mt * 16 + (lid >> 2) + ((r >> 1) ? 8 : 0);
                const int t2 = wc * 16 + nt * 8 + (lid & 3) * 2 + (r & 1);
                float pv = 0.f;
                if (t1 >= t2)
                    pv = __expf(s_cum[t1] - s_cum[t2]) * gacc[mt][nt][r] * s_dt[t2];
                const __nv_bfloat16 hb = __float2bfloat16(pv);
                const __nv_bfloat16 lb = __float2bfloat16(pv - __bfloat162float(hb));
                *(unsigned short*)(smem + SM_PH + t1 * PX + t2 * 2) =
                    __bfloat16_as_ushort(hb);
                *(unsigned short*)(smem + SM_PL + t1 * PX + t2 * 2) =
                    __bfloat16_as_ushort(lb);
            }
    __syncthreads();

    // ---- Y_intra = P·X (64x64, K=64): A=P[t][j], B-op=X[p][j] ----
    {
        float yacc[2][2][4];
#pragma unroll
        for (int i = 0; i < 2; i++)
#pragma unroll
            for (int j = 0; j < 2; j++)
#pragma unroll
                for (int k = 0; k < 4; k++) yacc[i][j][k] = 0.f;
#pragma unroll
        for (int ks = 0; ks < 4; ++ks) {
            uint32_t ah[2][4], al[2][4], bh2[2][2], bl2[2][2];
            const int arow = wr * 32 + (lid & 15);
            const int akc  = ks * 2 + (lid >> 4);
#pragma unroll
            for (int mt = 0; mt < 2; ++mt) {
                const uint32_t a = sb + SM_PH + (arow + mt * 16) * PX + akc * 16;
                ldmatrix_x4(ah[mt], a);
                ldmatrix_x4(al[mt], a + (SM_PL - SM_PH));
            }
            const int brow = wc * 16 + (lid & 7);
            const int bkc  = ks * 2 + ((lid >> 3) & 1);
#pragma unroll
            for (int nt = 0; nt < 2; ++nt) {
                const uint32_t bp = sb + SM_XH + (brow + nt * 8) * PX + bkc * 16;
                ldmatrix_x2(bh2[nt], bp);
                ldmatrix_x2(bl2[nt], bp + (SM_XL - SM_XH));
            }
#pragma unroll
            for (int mt = 0; mt < 2; ++mt)
#pragma unroll
                for (int nt = 0; nt < 2; ++nt) {
                    mma_bf16(yacc[mt][nt], ah[mt], bh2[nt]);
                    mma_bf16(yacc[mt][nt], ah[mt], bl2[nt]);
                    mma_bf16(yacc[mt][nt], al[mt], bh2[nt]);
                }
        }
        // store Y_intra
#pragma unroll
        for (int mt = 0; mt < 2; ++mt)
#pragma unroll
            for (int nt = 0; nt < 2; ++nt) {
                const int t0 = wr * 32 + mt * 16 + (lid >> 2);
                const int p0 = wc * 16 + nt * 8 + (lid & 3) * 2;
                *(float2*)(g_y + (tb + t0) * DINNER + h * HEADDIM + p0) =
                    make_float2(yacc[mt][nt][0], yacc[mt][nt][1]);
                *(float2*)(g_y + (tb + t0 + 8) * DINNER + h * HEADDIM + p0) =
                    make_float2(yacc[mt][nt][2], yacc[mt][nt][3]);
            }
    }
    __syncthreads();   // all P reads done; reuse P region for Xw

    // ---- Xw[p][j] = x[j,p] * w_j  into P region ----
    {
        const int p = tid >> 2, j0 = (tid & 3) * 16;
#pragma unroll
        for (int j = 0; j < 16; ++j) {
            const int jj = j0 + j;
            const float xv =
                __bfloat162float(__ushort_as_bfloat16(
                    *(unsigned short*)(smem + SM_XH + p * PX + jj * 2))) +
                __bfloat162float(__ushort_as_bfloat16(
                    *(unsigned short*)(smem + SM_XL + p * PX + jj * 2)));
            const float xw = xv * s_w[jj];
            const __nv_bfloat16 hb = __float2bfloat16(xw);
            const __nv_bfloat16 lb = __float2bfloat16(xw - __bfloat162float(hb));
            *(unsigned short*)(smem + SM_PH + p * PX + jj * 2) =
                __bfloat16_as_ushort(hb);
            *(unsigned short*)(smem + SM_PL + p * PX + jj * 2) =
                __bfloat16_as_ushort(lb);
        }
    }
    __syncthreads();

    // ---- L = Xw·B (64p x 128n, K=64): warp tile 32x32 (mt2 x nt4), trans B ----
    {
        float lacc[2][4][4];
#pragma unroll
        for (int i = 0; i < 2; i++)
#pragma unroll
            for (int j = 0; j < 4; j++)
#pragma unroll
                for (int k = 0; k < 4; k++) lacc[i][j][k] = 0.f;
#pragma unroll
        for (int ks = 0; ks < 4; ++ks) {
            uint32_t ah[2][4], al[2][4];
            const int arow = wr * 32 + (lid & 15);
            const int akc  = ks * 2 + (lid >> 4);
#pragma unroll
            for (int mt = 0; mt < 2; ++mt) {
                const uint32_t a = sb + SM_PH + (arow + mt * 16) * PX + akc * 16;
                ldmatrix_x4(ah[mt], a);
                ldmatrix_x4(al[mt], a + (SM_PL - SM_PH));
            }
            const int j0 = ks * 16 + (lid & 15);
#pragma unroll
            for (int nt = 0; nt < 4; ++nt) {
                const int n0 = wc * 32 + nt * 8;
                uint32_t bh2[2], bl2[2];
                const uint32_t bp = sb + SM_BH + j0 * PB + n0 * 2;
                ldmatrix_x2_trans(bh2, bp);
                ldmatrix_x2_trans(bl2, bp + (SM_BL - SM_BH));
#pragma unroll
                for (int mt = 0; mt < 2; ++mt) {
                    mma_bf16(lacc[mt][nt], ah[mt], bh2);
                    mma_bf16(lacc[mt][nt], ah[mt], bl2);
                    mma_bf16(lacc[mt][nt], al[mt], bh2);
                }
            }
        }
        float* Lout = g_cstate +
            (((size_t)b * NHEADS + h) * NCH + ch) * (HEADDIM * DSTATE);
#pragma unroll
        for (int mt = 0; mt < 2; ++mt)
#pragma unroll
            for (int nt = 0; nt < 4; ++nt) {
                const int p0 = wr * 32 + mt * 16 + (lid >> 2);
                const int n0 = wc * 32 + nt * 8 + (lid & 3) * 2;
                *(float2*)(Lout + (size_t)p0 * DSTATE + n0) =
                    make_float2(lacc[mt][nt][0], lacc[mt][nt][1]);
                *(float2*)(Lout + (size_t)(p0 + 8) * DSTATE + n0) =
                    make_float2(lacc[mt][nt][2], lacc[mt][nt][3]);
            }
    }
}

// ---------------------------------------------------------------------------
// Sequential combine over chunks: istate[c] = S_c;  S_{c+1} = ptot_c*S_c + L_c
// grid (NHEADS, BATCH), 256 threads x 32 floats.
// ---------------------------------------------------------------------------
__global__ __launch_bounds__(256) void combine_kernel()
{
    const int h = blockIdx.x, b = blockIdx.y;
    const int tid = threadIdx.x;
    const size_t off = (size_t)tid * 32;
    float4 acc[8];
#pragma unroll
    for (int r = 0; r < 8; r++) acc[r] = make_float4(0.f, 0.f, 0.f, 0.f);

    for (int c = 0; c < NCH; ++c) {
        const size_t base = (((size_t)b * NHEADS + h) * NCH + c) * (HEADDIM * DSTATE);
#pragma unroll
        for (int r = 0; r < 8; r++)
            *(float4*)(g_istate + base + off + r * 4) = acc[r];
        const float P = g_ptot[((size_t)b * NHEADS + h) * NCH + c];
#pragma unroll
        for (int r = 0; r < 8; r++) {
            const float4 f = *(const float4*)(g_cstate + base + off + r * 4);
            acc[r].x = fmaf(acc[r].x, P, f.x);
            acc[r].y = fmaf(acc[r].y, P, f.y);
            acc[r].z = fmaf(acc[r].z, P, f.z);
            acc[r].w = fmaf(acc[r].w, P, f.w);
        }
    }
}

// ---------------------------------------------------------------------------
// Inter-chunk: Y[t,p] += ecum_t * (C_t · S0[p,:])  — 64x64 GEMM, K=128.
// grid (NCH-1, NHEADS, BATCH), 256 threads (8 warps 2x4), bf16x3.
// ---------------------------------------------------------------------------
#define ISM_CH 0
#define ISM_CL 17408
#define ISM_SH 34816
#define ISM_SL 52224
#define ISM_EC 69632
#define INTER_SMEM 69888

__global__ void __launch_bounds__(256) void_guard();  // (unused fwd decl guard)

__global__ void __launch_bounds__(256) inter_kernel()
{
    extern __shared__ __align__(128) char smem[];
    const uint32_t sb = smem_u32(smem);
    const int ch = blockIdx.x + 1, h = blockIdx.y, b = blockIdx.z;
    const int tid = threadIdx.x;
    const int wid = tid >> 5, lid = tid & 31;
    const int wr = wid & 1, wc = wid >> 1;
    const size_t tb = (size_t)b * SEQLEN + (size_t)ch * CT;

    // stage C (t x n) and S0 (p x n), both pitch PB; 256 threads
    {
        const int row = tid >> 2, c0 = (tid & 3) * 32;
        const float* csrc = g_conv + (tb + row) * CONVDIM + DINNER + DSTATE;
        const float* ssrc = g_istate +
            (((size_t)b * NHEADS + h) * NCH + ch) * (HEADDIM * DSTATE) +
            (size_t)row * DSTATE;
#pragma unroll
        for (int c = 0; c < 32; c += 4) {
            float4 v = *(const float4*)(csrc + c0 + c);
            uint2 hi, lo; split4(v, hi, lo);
            *(uint2*)(smem + ISM_CH + row * PB + (c0 + c) * 2) = hi;
            *(uint2*)(smem + ISM_CL + row * PB + (c0 + c) * 2) = lo;
            float4 u = *(const float4*)(ssrc + c0 + c);
            split4(u, hi, lo);
            *(uint2*)(smem + ISM_SH + row * PB + (c0 + c) * 2) = hi;
            *(uint2*)(smem + ISM_SL + row * PB + (c0 + c) * 2) = lo;
        }
    }
    if (tid < 64)
        ((float*)(smem + ISM_EC))[tid] = g_ecum[(tb + tid) * NHEADS + h];
    __syncthreads();

    float acc[2][2][4];
#pragma unroll
    for (int i = 0; i < 2; i++)
#pragma unroll
        for (int j = 0; j < 2; j++)
#pragma unroll
            for (int k = 0; k < 4; k++) acc[i][j][k] = 0.f;

#pragma unroll
    for (int ks = 0; ks < 8; ++ks) {
        uint32_t ah[2][4], al[2][4], bh2[2][2], bl2[2][2];
        const int arow = wr * 32 + (lid & 15);
        const int akc  = ks * 2 + (lid >> 4);
#pragma unroll
        for (int mt = 0; mt < 2; ++mt) {
            const uint32_t a = sb + ISM_CH + (arow + mt * 16) * PB + akc * 16;
            ldmatrix_x4(ah[mt], a);
            ldmatrix_x4(al[mt], a + (ISM_CL - ISM_CH));
        }
        const int brow = wc * 16 + (lid & 7);
        const int bkc  = ks * 2 + ((lid >> 3) & 1);
#pragma unroll
        for (int nt = 0; nt < 2; ++nt) {
            const uint32_t bp = sb + ISM_SH + (brow + nt * 8) * PB + bkc * 16;
            ldmatrix_x2(bh2[nt], bp);
            ldmatrix_x2(bl2[nt], bp + (ISM_SL - ISM_SH));
        }
#pragma unroll
        for (int mt = 0; mt < 2; ++mt)
#pragma unroll
            for (int nt = 0; nt < 2; ++nt) {
                mma_bf16(acc[mt][nt], ah[mt], bh2[nt]);
                mma_bf16(acc[mt][nt], ah[mt], bl2[nt]);
                mma_bf16(acc[mt][nt], al[mt], bh2[nt]);
            }
    }

    const float* s_ec = (const float*)(smem + ISM_EC);
#pragma unroll
    for (int mt = 0; mt < 2; ++mt)
#pragma unroll
        for (int nt = 0; nt < 2; ++nt) {
            const int t0 = wr * 32 + mt * 16 + (lid >> 2);
            const int p0 = wc * 16 + nt * 8 + (lid & 3) * 2;
            {
                float* yp = g_y + (tb + t0) * DINNER + h * HEADDIM + p0;
                float2 o = *(float2*)yp;
                o.x += s_ec[t0] * acc[mt][nt][0];
                o.y += s_ec[t0] * acc[mt][nt][1];
                *(float2*)yp = o;
            }
            {
                float* yp = g_y + (tb + t0 + 8) * DINNER + h * HEADDIM + p0;
                float2 o = *(float2*)yp;
                o.x += s_ec[t0 + 8] * acc[mt][nt][2];
                o.y += s_ec[t0 + 8] * acc[mt][nt][3];
                *(float2*)yp = o;
            }
        }
}

// ---------------------------------------------------------------------------
// y += x*D; yz = y*silu(z); RMSNorm(yz) * norm_w  -> bf16 hi/lo (GEMM2 input)
// ---------------------------------------------------------------------------
__global__ __launch_bounds__(256) void gate_norm_kernel(
    const float* __restrict__ Dv, const float* __restrict__ nw)
{
    const int bt = blockIdx.x;
    const float* zrow = g_zx   + (size_t)bt * DINPROJ;
    const float* xrow = g_conv + (size_t)bt * CONVDIM;
    const float* yrow = g_y    + (size_t)bt * DINNER;

    float v[6];
    float ss = 0.f;
#pragma unroll
    for (int i = 0; i < 6; i++) {
        const int c = threadIdx.x + i * 256;
        const float yv = fmaf(xrow[c], Dv[c >> 6], yrow[c]);
        const float z  = zrow[c];
        const float gz = z / (1.f + __expf(-z));
        const float val = yv * gz;
        v[i] = val;
        ss = fmaf(val, val, ss);
    }
#pragma unroll
    for (int o = 16; o; o >>= 1) ss += __shfl_xor_sync(0xffffffffu, ss, o);
    __shared__ float sred[8];
    if ((threadIdx.x & 31) == 0) sred[threadIdx.x >> 5] = ss;
    __syncthreads();
    float tot = 0.f;
#pragma unroll
    for (int i = 0; i < 8; i++) tot += sred[i];
    const float scale = rsqrtf(tot * (1.f / DINNER) + 1e-5f);

    __nv_bfloat16* yh = g_yn_hi + (size_t)bt * DINNER;
    __nv_bfloat16* yl = g_yn_lo + (size_t)bt * DINNER;
#pragma unroll
    for (int i = 0; i < 6; i++) {
        const int c = threadIdx.x + i * 256;
        const float val = v[i] * scale * nw[c];
        const __nv_bfloat16 hb = __float2bfloat16(val);
        yh[c] = hb;
        yl[c] = __float2bfloat16(val - __bfloat162float(hb));
    }
}

// ---------------------------------------------------------------------------
// Launch
// ---------------------------------------------------------------------------
extern "C" void kernel_launch(void* const* d_in, const int* in_sizes, int n_in,
                              void* d_out, int out_size)
{
    const float* u          = (const float*)d_in[0];
    const float* in_proj_w  = (const float*)d_in[1];
    const float* conv_w     = (const float*)d_in[2];
    const float* conv_b     = (const float*)d_in[3];
    const float* dt_bias    = (const float*)d_in[4];
    const float* A_log      = (const float*)d_in[5];
    const float* Dv         = (const float*)d_in[6];
    const float* norm_w     = (const float*)d_in[7];
    const float* out_proj_w = (const float*)d_in[8];
    float* out = (float*)d_out;

    float* zx = nullptr;
    __nv_bfloat16 *uh, *ul, *w1h, *w1l, *w2h, *w2l, *ynh, *ynl;
    cudaGetSymbolAddress((void**)&zx,  g_zx);
    cudaGetSymbolAddress((void**)&uh,  g_u_hi);
    cudaGetSymbolAddress((void**)&ul,  g_u_lo);
    cudaGetSymbolAddress((void**)&w1h, g_w1_hi);
    cudaGetSymbolAddress((void**)&w1l, g_w1_lo);
    cudaGetSymbolAddress((void**)&w2h, g_w2_hi);
    cudaGetSymbolAddress((void**)&w2l, g_w2_lo);
    cudaGetSymbolAddress((void**)&ynh, g_yn_hi);
    cudaGetSymbolAddress((void**)&ynl, g_yn_lo);

    cudaFuncSetAttribute(gemm_mma,
                         cudaFuncAttributeMaxDynamicSharedMemorySize, GEMM_SMEM);
    cudaFuncSetAttribute(chunk_kernel,
                         cudaFuncAttributeMaxDynamicSharedMemorySize, CHUNK_SMEM);
    cudaFuncSetAttribute(inter_kernel,
                         cudaFuncAttributeMaxDynamicSharedMemorySize, INTER_SMEM);

    // 0) bf16 hi/lo splits for GEMM operands
    split_kernel<<<(NTOK * DMODEL + 255) / 256, 256>>>(u, uh, ul, NTOK * DMODEL);
    split_kernel<<<(DINPROJ * DMODEL + 255) / 256, 256>>>(in_proj_w, w1h, w1l,
                                                          DINPROJ * DMODEL);
    split_kernel<<<(DMODEL * DINNER + 255) / 256, 256>>>(out_proj_w, w2h, w2l,
                                                         DMODEL * DINNER);

    // 1) zxbcdt = u @ in_proj_w^T   — HMMA bf16x3
    dim3 g1((DINPROJ + 127) / 128, NTOK / 128);
    gemm_mma<<<g1, 256, GEMM_SMEM>>>(uh, ul, w1h, w1l, zx,
                                     NTOK, DINPROJ, DMODEL);

    // 2) depthwise causal conv + silu
    conv_silu_kernel<<<(NTOK * CONVDIM + 255) / 256, 256>>>(conv_w, conv_b);

    // 3) dt softplus / log-decay a
    dt_kernel<<<(NTOK * NHEADS + 255) / 256, 256>>>(dt_bias, A_log);

    // 4) SSD chunk pass — tensor cores, 256 threads
    chunk_kernel<<<dim3(NCH, NHEADS, BATCH), 256, CHUNK_SMEM>>>();

    // 5) combine chunk states sequentially
    combine_kernel<<<dim3(NHEADS, BATCH), 256>>>();

    // 6) inter-chunk contribution — tensor cores, 256 threads
    inter_kernel<<<dim3(NCH - 1, NHEADS, BATCH), 256, INTER_SMEM>>>();

    // 7) gate + RMSNorm -> bf16 hi/lo
    gate_norm_kernel<<<NTOK, 256>>>(Dv, norm_w);

    // 8) out = yn @ out_proj_w^T — HMMA bf16x3
    dim3 g2((DMODEL + 127) / 128, NTOK / 128);
    gemm_mma<<<g2, 256, GEMM_SMEM>>>(ynh, ynl, w2h, w2l, out,
                                     NTOK, DMODEL, DINNER);
}